// round 15
// baseline (speedup 1.0000x reference)
#include <cuda_runtime.h>
#include <cuda_bf16.h>
#include <math.h>
#include <stdint.h>

#define DIM 768
#define NTOK 1024
#define BATCH 4
#define ROWS (BATCH * NTOK)        // 4096
#define F_DIM 256
#define HEADS 12
#define DHEAD 64
#define QKV3 (3 * DIM)             // 2304
#define MLPD 3072
#define DEPTH 8
#define LN_EPS 1e-5f

// per-layer weight-scale layout: [qkv 2304][out 768][m1 3072][m2 768]
#define SOFF_QKV 0
#define SOFF_OUT 2304
#define SOFF_M1  3072
#define SOFF_M2  6144
#define SC_PER_L 6912
#define SC_TOTAL (DEPTH * SC_PER_L)

// ============================================================================
// Helpers
// ============================================================================
__device__ __forceinline__ uint32_t smem_u32(const void* p) {
    uint32_t a;
    asm("{ .reg .u64 t; cvta.to.shared.u64 t, %1; cvt.u32.u64 %0, t; }"
        : "=r"(a) : "l"(p));
    return a;
}
#define SW128(o) ((o) ^ (((o) >> 3) & 0x70))

__device__ __forceinline__ void cp16(uint32_t s, const void* g) {
    asm volatile("cp.async.cg.shared.global [%0], [%1], 16;" :: "r"(s), "l"(g));
}
#define CP_COMMIT() asm volatile("cp.async.commit_group;" ::: "memory")
#define CP_WAIT1()  asm volatile("cp.async.wait_group 1;" ::: "memory")

#define LDSM_X4(r0, r1, r2, r3, addr) \
    asm volatile("ldmatrix.sync.aligned.m8n8.x4.shared.b16 {%0,%1,%2,%3}, [%4];" \
        : "=r"(r0), "=r"(r1), "=r"(r2), "=r"(r3) : "r"(addr))
#define LDSM_X4_T(r0, r1, r2, r3, addr) \
    asm volatile("ldmatrix.sync.aligned.m8n8.x4.trans.shared.b16 {%0,%1,%2,%3}, [%4];" \
        : "=r"(r0), "=r"(r1), "=r"(r2), "=r"(r3) : "r"(addr))

__device__ __forceinline__ void mma_bf16(float* c, const uint32_t* a, const uint32_t* b) {
    asm volatile(
        "mma.sync.aligned.m16n8k16.row.col.f32.bf16.bf16.f32 "
        "{%0,%1,%2,%3}, {%4,%5,%6,%7}, {%8,%9}, {%0,%1,%2,%3};"
        : "+f"(c[0]), "+f"(c[1]), "+f"(c[2]), "+f"(c[3])
        : "r"(a[0]), "r"(a[1]), "r"(a[2]), "r"(a[3]), "r"(b[0]), "r"(b[1]));
}
__device__ __forceinline__ void mma4(float* c, const uint32_t* a, uint32_t b0, uint32_t b1) {
    uint32_t b[2] = { b0, b1 };
    mma_bf16(c, a, b);
}
__device__ __forceinline__ void mma_s8(int* c, const uint32_t* a, uint32_t b0, uint32_t b1) {
    asm volatile(
        "mma.sync.aligned.m16n8k32.row.col.s32.s8.s8.s32 "
        "{%0,%1,%2,%3}, {%4,%5,%6,%7}, {%8,%9}, {%0,%1,%2,%3};"
        : "+r"(c[0]), "+r"(c[1]), "+r"(c[2]), "+r"(c[3])
        : "r"(a[0]), "r"(a[1]), "r"(a[2]), "r"(a[3]), "r"(b0), "r"(b1));
}

__device__ __forceinline__ void split2(float v, __nv_bfloat16& h, __nv_bfloat16& l) {
    h = __float2bfloat16(v);
    l = __float2bfloat16(v - __bfloat162float(h));
}
__device__ __forceinline__ void pack_split(float a, float b, uint32_t& hi, uint32_t& lo) {
    __nv_bfloat16 ha = __float2bfloat16(a);
    __nv_bfloat16 hb = __float2bfloat16(b);
    __nv_bfloat162 H(ha, hb);
    __nv_bfloat162 L(__float2bfloat16(a - __bfloat162float(ha)),
                     __float2bfloat16(b - __bfloat162float(hb)));
    hi = *(uint32_t*)&H;
    lo = *(uint32_t*)&L;
}
__device__ __forceinline__ float gelu_f(float v) {
    return 0.5f * v * (1.0f + erff(v * 0.7071067811865475f));
}
__device__ __forceinline__ void quant1(float v, float s, float inv, int& q1, int& q2) {
    float f1 = rintf(v * inv);
    f1 = fminf(fmaxf(f1, -127.f), 127.f);
    float r = (v - f1 * s) * inv * 128.f;
    float f2 = fminf(fmaxf(rintf(r), -127.f), 127.f);
    q1 = (int)f1; q2 = (int)f2;
}
__device__ __forceinline__ uint32_t pack4(int a, int b, int c, int d) {
    return (uint32_t)(a & 255) | ((uint32_t)(b & 255) << 8) |
           ((uint32_t)(c & 255) << 16) | ((uint32_t)(d & 255) << 24);
}

// ============================================================================
// Scratch (device globals)
// ============================================================================
__device__ __align__(16) float g_x  [ROWS * DIM];
__device__ __align__(16) float g_part[2 * ROWS * DIM];
__device__ __align__(16) float g_of [ROWS * DIM];
__device__ __align__(16) float g_hf [ROWS * MLPD];
__device__ __align__(16) __nv_bfloat16 g_qh[ROWS * QKV3], g_ql[ROWS * QKV3];
// int8 activations (2 slices + per-row scale)
__device__ __align__(16) int8_t g_y1[ROWS * DIM],  g_y2[ROWS * DIM];
__device__ __align__(16) int8_t g_o1[ROWS * DIM],  g_o2[ROWS * DIM];
__device__ __align__(16) int8_t g_h1[ROWS * MLPD], g_h2[ROWS * MLPD];
__device__ float g_sy[ROWS], g_so[ROWS], g_sh[ROWS];
// int8 weights [L][N][K] (2 slices) + scales
__device__ __align__(16) int8_t g_qkvq1[DEPTH * QKV3 * DIM], g_qkvq2[DEPTH * QKV3 * DIM];
__device__ __align__(16) int8_t g_outq1[DEPTH * DIM * DIM],  g_outq2[DEPTH * DIM * DIM];
__device__ __align__(16) int8_t g_m1q1 [DEPTH * MLPD * DIM], g_m1q2 [DEPTH * MLPD * DIM];
__device__ __align__(16) int8_t g_m2q1 [DEPTH * DIM * MLPD], g_m2q2 [DEPTH * DIM * MLPD];
__device__ uint32_t g_wsb[SC_TOTAL];
__device__ float    g_wscf[SC_TOTAL];

// ============================================================================
// Weight quantization (runs once per call)
// ============================================================================
__global__ void zero_scales_kernel(uint32_t* s, int n) {
    int i = blockIdx.x * 256 + threadIdx.x;
    if (i < n) s[i] = 0;
}

#define WL_BLOCKS 6912
__device__ __forceinline__ void wq_dispatch(
    int r, const float* qkv_w, const float* out_w,
    const float* m1w, const float* m2w,
    int8_t* qkv1, int8_t* qkv2, int8_t* out1, int8_t* out2,
    int8_t* m11, int8_t* m12, int8_t* m21, int8_t* m22,
    const float*& w, int8_t*& d1, int8_t*& d2,
    int& K, int& N, int& nx, int& ny, int& soff)
{
    if (r < 1728)      { w = qkv_w; d1 = qkv1; d2 = qkv2; K = DIM;  N = QKV3; nx = r % 72; ny = r / 72; soff = SOFF_QKV; }
    else if (r < 2304) { int rr = r - 1728; w = out_w; d1 = out1; d2 = out2; K = DIM;  N = DIM;  nx = rr % 24; ny = rr / 24; soff = SOFF_OUT; }
    else if (r < 4608) { int rr = r - 2304; w = m1w;  d1 = m11;  d2 = m12;  K = DIM;  N = MLPD; nx = rr % 96; ny = rr / 96; soff = SOFF_M1; }
    else               { int rr = r - 4608; w = m2w;  d1 = m21;  d2 = m22;  K = MLPD; N = DIM;  nx = rr % 24; ny = rr / 24; soff = SOFF_M2; }
}

__global__ void wq_max_kernel(
    const float* __restrict__ qkv_w, const float* __restrict__ out_w,
    const float* __restrict__ m1w,   const float* __restrict__ m2w,
    uint32_t* __restrict__ scales)
{
    int z = blockIdx.x;
    int l = z / WL_BLOCKS, r = z % WL_BLOCKS;
    const float* w; int8_t *d1, *d2; int K, N, nx, ny, soff;
    wq_dispatch(r, qkv_w, out_w, m1w, m2w,
                nullptr, nullptr, nullptr, nullptr, nullptr, nullptr, nullptr, nullptr,
                w, d1, d2, K, N, nx, ny, soff);
    int n0 = nx * 32, k0 = ny * 32;
    int tx = threadIdx.x, ty = threadIdx.y;
    const float* wl = w + (size_t)l * K * N;
    float m = 0.f;
    for (int i = ty; i < 32; i += 8)
        m = fmaxf(m, fabsf(wl[(size_t)(k0 + i) * N + n0 + tx]));
    __shared__ float red[8][33];
    red[ty][tx] = m;
    __syncthreads();
    if (ty == 0) {
        #pragma unroll
        for (int j = 1; j < 8; j++) m = fmaxf(m, red[j][tx]);
        atomicMax(scales + l * SC_PER_L + soff + n0 + tx, __float_as_uint(m));
    }
}

__global__ void wq_finalize_kernel(const uint32_t* sb, float* sf, int n) {
    int i = blockIdx.x * 256 + threadIdx.x;
    if (i < n) sf[i] = __uint_as_float(sb[i]) * (1.0f / 127.0f);
}

__global__ void wq_write_kernel(
    const float* __restrict__ qkv_w, const float* __restrict__ out_w,
    const float* __restrict__ m1w,   const float* __restrict__ m2w,
    const float* __restrict__ sf,
    int8_t* qkv1, int8_t* qkv2, int8_t* out1, int8_t* out2,
    int8_t* m11, int8_t* m12, int8_t* m21, int8_t* m22)
{
    int z = blockIdx.x;
    int l = z / WL_BLOCKS, r = z % WL_BLOCKS;
    const float* w; int8_t *d1, *d2; int K, N, nx, ny, soff;
    wq_dispatch(r, qkv_w, out_w, m1w, m2w,
                qkv1, qkv2, out1, out2, m11, m12, m21, m22,
                w, d1, d2, K, N, nx, ny, soff);
    __shared__ float t[32][33];
    int n0 = nx * 32, k0 = ny * 32;
    int tx = threadIdx.x, ty = threadIdx.y;
    const float* wl = w + (size_t)l * K * N;
    for (int i = ty; i < 32; i += 8)
        t[i][tx] = wl[(size_t)(k0 + i) * N + n0 + tx];
    __syncthreads();
    size_t ob = (size_t)l * K * N;
    const float* sfl = sf + l * SC_PER_L + soff;
    for (int i = ty; i < 32; i += 8) {
        int n = n0 + i;
        float s = sfl[n];
        float inv = (s > 0.f) ? 1.0f / s : 0.f;
        float v = t[tx][i];                 // = wl[k0+tx][n]
        int q1, q2;
        quant1(v, s, inv, q1, q2);
        size_t o = ob + (size_t)n * K + k0 + tx;
        d1[o] = (int8_t)q1; d2[o] = (int8_t)q2;
    }
}

// ============================================================================
// Embed GEMM with fused sine pos-embed
// ============================================================================
__device__ __forceinline__ float posval(int n, int d) {
    int r = n >> 5, c = n & 31;
    int id = (d < 384) ? d : d - 384;
    float coord = (d < 384) ? (float)(r + 1) : (float)(c + 1);
    float ang = coord * (6.283185307179586f / (32.0f + 1e-6f));
    float ex = (float)(2 * (id / 2)) * (1.0f / 384.0f);
    float p = ang / __powf(10000.0f, ex);
    return (id & 1) ? cosf(p) : sinf(p);
}

__global__ __launch_bounds__(256) void embed_kernel(
    const float* __restrict__ cf, const float* __restrict__ w,
    const float* __restrict__ bias, float* __restrict__ x)
{
    __shared__ float As[16][64];
    __shared__ float Bs[16][68];
    int b  = blockIdx.z;
    int n0 = blockIdx.x * 64, d0 = blockIdx.y * 64;
    int tid = threadIdx.x;
    int ty = tid / 16, tx = tid % 16;
    float acc[4][4] = {};
    const float* cfb = cf + (size_t)b * F_DIM * NTOK;
    for (int k0 = 0; k0 < F_DIM; k0 += 16) {
        #pragma unroll
        for (int it = 0; it < 4; it++) {
            int idx = tid + it * 256;
            As[idx >> 6][idx & 63] = cfb[(size_t)(k0 + (idx >> 6)) * NTOK + n0 + (idx & 63)];
        }
        #pragma unroll
        for (int it = 0; it < 4; it++) {
            int idx = tid + it * 256;
            Bs[idx & 15][idx >> 4] = w[(size_t)(d0 + (idx >> 4)) * F_DIM + k0 + (idx & 15)];
        }
        __syncthreads();
        #pragma unroll
        for (int kk = 0; kk < 16; kk++) {
            float a[4], bb[4];
            #pragma unroll
            for (int i = 0; i < 4; i++) a[i]  = As[kk][ty * 4 + i];
            #pragma unroll
            for (int j = 0; j < 4; j++) bb[j] = Bs[kk][tx * 4 + j];
            #pragma unroll
            for (int i = 0; i < 4; i++)
                #pragma unroll
                for (int j = 0; j < 4; j++)
                    acc[i][j] += a[i] * bb[j];
        }
        __syncthreads();
    }
    #pragma unroll
    for (int i = 0; i < 4; i++) {
        int n = n0 + ty * 4 + i;
        #pragma unroll
        for (int j = 0; j < 4; j++) {
            int d = d0 + tx * 4 + j;
            x[((size_t)b * NTOK + n) * DIM + d] = acc[i][j] + bias[d] + posval(n, d);
        }
    }
}

// ============================================================================
// LayerNorm -> int8 x2 quantize.  Warp-per-row.  Optional fused split-K
// reduce (x += part0 + part1 + rbias).
// ============================================================================
__global__ __launch_bounds__(256) void ln_quant_kernel(
    const float* __restrict__ part, const float* __restrict__ rbias,
    float* __restrict__ x, const float* __restrict__ w,
    const float* __restrict__ bias,
    int8_t* __restrict__ q1o, int8_t* __restrict__ q2o,
    float* __restrict__ sco)
{
    int warp = threadIdx.x >> 5, lane = threadIdx.x & 31;
    int row = blockIdx.x * 8 + warp;
    float4* xr = (float4*)(x + (size_t)row * DIM);
    float4 v[6];
    float s = 0.f, ss = 0.f;
    if (part) {
        const float4* p0 = (const float4*)(part + (size_t)row * DIM);
        const float4* p1 = (const float4*)(part + (size_t)(ROWS + row) * DIM);
        const float4* rb = (const float4*)rbias;
        #pragma unroll
        for (int i = 0; i < 6; i++) {
            int idx4 = lane + i * 32;
            float4 a = p0[idx4], b = p1[idx4], bb = rb[idx4];
            v[i] = xr[idx4];
            v[i].x += a.x + b.x + bb.x;
            v[i].y += a.y + b.y + bb.y;
            v[i].z += a.z + b.z + bb.z;
            v[i].w += a.w + b.w + bb.w;
            xr[idx4] = v[i];
            s  += v[i].x + v[i].y + v[i].z + v[i].w;
            ss += v[i].x * v[i].x + v[i].y * v[i].y + v[i].z * v[i].z + v[i].w * v[i].w;
        }
    } else {
        #pragma unroll
        for (int i = 0; i < 6; i++) {
            v[i] = xr[lane + i * 32];
            s  += v[i].x + v[i].y + v[i].z + v[i].w;
            ss += v[i].x * v[i].x + v[i].y * v[i].y + v[i].z * v[i].z + v[i].w * v[i].w;
        }
    }
    #pragma unroll
    for (int off = 16; off; off >>= 1) {
        s  += __shfl_xor_sync(0xffffffffu, s,  off);
        ss += __shfl_xor_sync(0xffffffffu, ss, off);
    }
    float mu  = s * (1.0f / DIM);
    float var = ss * (1.0f / DIM) - mu * mu;
    float inv = rsqrtf(var + LN_EPS);
    const float4* wv = (const float4*)w;
    const float4* bv = (const float4*)bias;
    float mx = 0.f;
    #pragma unroll
    for (int i = 0; i < 6; i++) {
        int idx4 = lane + i * 32;
        float4 ww = wv[idx4], bb = bv[idx4];
        v[i].x = (v[i].x - mu) * inv * ww.x + bb.x;
        v[i].y = (v[i].y - mu) * inv * ww.y + bb.y;
        v[i].z = (v[i].z - mu) * inv * ww.z + bb.z;
        v[i].w = (v[i].w - mu) * inv * ww.w + bb.w;
        mx = fmaxf(mx, fmaxf(fmaxf(fabsf(v[i].x), fabsf(v[i].y)),
                             fmaxf(fabsf(v[i].z), fabsf(v[i].w))));
    }
    #pragma unroll
    for (int off = 16; off; off >>= 1)
        mx = fmaxf(mx, __shfl_xor_sync(0xffffffffu, mx, off));
    float sq = mx * (1.0f / 127.0f);
    float invq = (mx > 0.f) ? 127.0f / mx : 0.f;
    if (lane == 0) sco[row] = sq;
    uint32_t* d1 = (uint32_t*)(q1o + (size_t)row * DIM);
    uint32_t* d2 = (uint32_t*)(q2o + (size_t)row * DIM);
    #pragma unroll
    for (int i = 0; i < 6; i++) {
        int idx4 = lane + i * 32;
        int a1, a2, b1, b2, c1, c2, e1, e2;
        quant1(v[i].x, sq, invq, a1, a2);
        quant1(v[i].y, sq, invq, b1, b2);
        quant1(v[i].z, sq, invq, c1, c2);
        quant1(v[i].w, sq, invq, e1, e2);
        d1[idx4] = pack4(a1, b1, c1, e1);
        d2[idx4] = pack4(a2, b2, c2, e2);
    }
}

// ============================================================================
// Activation quantize: fp32 [ROWS][C] -> int8 x2 + per-row scale. Warp/row.
// ============================================================================
__global__ __launch_bounds__(256) void act_quant_kernel(
    const float* __restrict__ x, int C4,
    int8_t* __restrict__ q1o, int8_t* __restrict__ q2o,
    float* __restrict__ sco)
{
    int warp = threadIdx.x >> 5, lane = threadIdx.x & 31;
    int row = blockIdx.x * 8 + warp;
    const float4* xr = (const float4*)(x + (size_t)row * (C4 * 4));
    float mx = 0.f;
    for (int i = lane; i < C4; i += 32) {
        float4 v = xr[i];
        mx = fmaxf(mx, fmaxf(fmaxf(fabsf(v.x), fabsf(v.y)),
                             fmaxf(fabsf(v.z), fabsf(v.w))));
    }
    #pragma unroll
    for (int off = 16; off; off >>= 1)
        mx = fmaxf(mx, __shfl_xor_sync(0xffffffffu, mx, off));
    float sq = mx * (1.0f / 127.0f);
    float invq = (mx > 0.f) ? 127.0f / mx : 0.f;
    if (lane == 0) sco[row] = sq;
    uint32_t* d1 = (uint32_t*)(q1o + (size_t)row * (C4 * 4));
    uint32_t* d2 = (uint32_t*)(q2o + (size_t)row * (C4 * 4));
    for (int i = lane; i < C4; i += 32) {
        float4 v = xr[i];
        int a1, a2, b1, b2, c1, c2, e1, e2;
        quant1(v.x, sq, invq, a1, a2);
        quant1(v.y, sq, invq, b1, b2);
        quant1(v.z, sq, invq, c1, c2);
        quant1(v.w, sq, invq, e1, e2);
        d1[i] = pack4(a1, b1, c1, e1);
        d2[i] = pack4(a2, b2, c2, e2);
    }
}

// ============================================================================
// int8 Ozaki GEMM via mma.sync m16n8k32 (2 slices, int32 accum).
// C[4096,N] = A[4096,K] @ Bt[N,K]^T, CTA tile 64x128, K-chunk 64, 3 stages,
// 2 CTAs/SM.  v = sA[row]*sB[col]*(acc1 + acc2/128).
// ============================================================================
#define ISTG 24576
#define IMMA_SMEM (3 * ISTG)   // 73728

__global__ __launch_bounds__(256, 2) void imma_gemm_kernel(
    int K, int N,
    const int8_t* __restrict__ A1, const int8_t* __restrict__ A2,
    const float* __restrict__ sA,
    const int8_t* __restrict__ B1, const int8_t* __restrict__ B2,
    const float* __restrict__ sB,
    const float* __restrict__ bias,
    float* __restrict__ outf,
    __nv_bfloat16* __restrict__ oh, __nv_bfloat16* __restrict__ ol,
    int gelu)
{
    extern __shared__ char smem[];
    uint32_t sbase = smem_u32(smem);
    int tid = threadIdx.x, wid = tid >> 5, lane = tid & 31;
    int n0 = blockIdx.x * 128, m0 = blockIdx.y * 64;

    int nch_tot = K / 64;
    int per = nch_tot / gridDim.z;
    int ch_begin = blockIdx.z * per;
    int chend = ch_begin + per;

    // cp.async addressing: A slices 64 rows x 64B; B slices 128 rows x 64B
    int rA = tid >> 2, cA = tid & 3;
    uint32_t so0 = SW128((uint32_t)(rA * 64 + cA * 16));
    uint32_t so1 = SW128((uint32_t)((rA + 64) * 64 + cA * 16));
    size_t gA  = (size_t)rA * K + cA * 16;
    size_t gB2 = (size_t)(rA + 64) * K + cA * 16;
    const char* pA1 = (const char*)(A1 + (size_t)m0 * K);
    const char* pA2 = (const char*)(A2 + (size_t)m0 * K);
    const char* pB1 = (const char*)(B1 + (size_t)n0 * K);
    const char* pB2 = (const char*)(B2 + (size_t)n0 * K);

#define ISSUE(CH) do { \
    if ((CH) < chend) { \
        uint32_t sb0 = sbase + (uint32_t)((CH) % 3) * ISTG; \
        size_t kb = (size_t)(CH) * 64; \
        cp16(sb0 +          so0, pA1 + kb + gA); \
        cp16(sb0 + 4096  +  so0, pA2 + kb + gA); \
        cp16(sb0 + 8192  +  so0, pB1 + kb + gA); \
        cp16(sb0 + 8192  +  so1, pB1 + kb + gB2); \
        cp16(sb0 + 16384 +  so0, pB2 + kb + gA); \
        cp16(sb0 + 16384 +  so1, pB2 + kb + gB2); \
    } \
    CP_COMMIT(); } while (0)

    int wm = wid >> 2, wn = wid & 3;        // 2m x 4n warps; warp tile 32x32
    uint32_t lrow = lane & 15, lhalf = lane >> 4;

    uint32_t aoff[2][2], boff[2][2];
    #pragma unroll
    for (int ks = 0; ks < 2; ks++) {
        uint32_t ko = lhalf * 16 + ks * 32;
        #pragma unroll
        for (int mf = 0; mf < 2; mf++)
            aoff[ks][mf] = SW128((uint32_t)((wm * 32 + mf * 16 + lrow) * 64) + ko);
        #pragma unroll
        for (int nf2 = 0; nf2 < 2; nf2++)
            boff[ks][nf2] = SW128((uint32_t)((wn * 32 + nf2 * 16 + lrow) * 64) + ko);
    }

    int acc1[2][4][4] = {}, acc2[2][4][4] = {};

    ISSUE(ch_begin);
    ISSUE(ch_begin + 1);

    for (int ch = ch_begin; ch < chend; ch++) {
        CP_WAIT1();
        __syncthreads();
        ISSUE(ch + 2);
        uint32_t st = sbase + (uint32_t)(ch % 3) * ISTG;
        #pragma unroll
        for (int ks = 0; ks < 2; ks++) {
            uint32_t a1[2][4], a2[2][4], b1[4][2], b2[4][2];
            #pragma unroll
            for (int mf = 0; mf < 2; mf++) {
                uint32_t a0 = st + aoff[ks][mf];
                LDSM_X4(a1[mf][0], a1[mf][1], a1[mf][2], a1[mf][3], a0);
                LDSM_X4(a2[mf][0], a2[mf][1], a2[mf][2], a2[mf][3], a0 + 4096);
            }
            #pragma unroll
            for (int nf2 = 0; nf2 < 2; nf2++) {
                uint32_t b0 = st + 8192 + boff[ks][nf2];
                uint32_t t0, t1, t2, t3;
                LDSM_X4(t0, t1, t2, t3, b0);
                b1[nf2 * 2][0] = t0; b1[nf2 * 2 + 1][0] = t1;
                b1[nf2 * 2][1] = t2; b1[nf2 * 2 + 1][1] = t3;
                LDSM_X4(t0, t1, t2, t3, b0 + 8192);
                b2[nf2 * 2][0] = t0; b2[nf2 * 2 + 1][0] = t1;
                b2[nf2 * 2][1] = t2; b2[nf2 * 2 + 1][1] = t3;
            }
            #pragma unroll
            for (int mf = 0; mf < 2; mf++) {
                #pragma unroll
                for (int nf = 0; nf < 4; nf++) {
                    mma_s8(acc1[mf][nf], a1[mf], b1[nf][0], b1[nf][1]);
                    mma_s8(acc2[mf][nf], a1[mf], b2[nf][0], b2[nf][1]);
                    mma_s8(acc2[mf][nf], a2[mf], b1[nf][0], b1[nf][1]);
                }
            }
        }
    }
#undef ISSUE

    // Epilogue: v = sA*sB*(acc1 + acc2/128) (+bias)(+gelu)
    float* myout = outf ? (outf + (size_t)blockIdx.z * ((size_t)ROWS * N)) : (float*)0;
    int g = lane >> 2, tg = lane & 3;
    #pragma unroll
    for (int mf = 0; mf < 2; mf++) {
        #pragma unroll
        for (int half = 0; half < 2; half++) {
            int row = m0 + wm * 32 + mf * 16 + g + half * 8;
            float sa = __ldg(sA + row);
            #pragma unroll
            for (int nf = 0; nf < 4; nf++) {
                int col = n0 + wn * 32 + nf * 8 + tg * 2;
                float sb0 = sa * __ldg(sB + col);
                float sb1 = sa * __ldg(sB + col + 1);
                float v0 = sb0 * ((float)acc1[mf][nf][half * 2 + 0] +
                                  (float)acc2[mf][nf][half * 2 + 0] * 0.0078125f);
                float v1 = sb1 * ((float)acc1[mf][nf][half * 2 + 1] +
                                  (float)acc2[mf][nf][half * 2 + 1] * 0.0078125f);
                if (bias) { v0 += __ldg(bias + col); v1 += __ldg(bias + col + 1); }
                if (gelu) { v0 = gelu_f(v0); v1 = gelu_f(v1); }
                size_t gb = (size_t)row * N + col;
                if (myout) {
                    *(float2*)(myout + gb) = make_float2(v0, v1);
                } else {
                    __nv_bfloat16 h0, l0, h1, l1;
                    split2(v0, h0, l0); split2(v1, h1, l1);
                    *(__nv_bfloat162*)(oh + gb) = __nv_bfloat162(h0, h1);
                    *(__nv_bfloat162*)(ol + gb) = __nv_bfloat162(l0, l1);
                }
            }
        }
    }
}

// ============================================================================
// Split-K reduce (only after last layer): x += p0 + p1 + bias
// ============================================================================
__global__ __launch_bounds__(256) void reduce_add_kernel(
    const float* __restrict__ part, const float* __restrict__ bias,
    float* __restrict__ x, int N)
{
    int i = blockIdx.x * 256 + threadIdx.x;
    const float4* p0 = (const float4*)part;
    const float4* p1 = p0 + ((size_t)ROWS * N) / 4;
    float4 a = p0[i], b = p1[i];
    float4 xx = ((const float4*)x)[i];
    float4 bb = ((const float4*)bias)[i & (N / 4 - 1)];
    xx.x += a.x + b.x + bb.x;
    xx.y += a.y + b.y + bb.y;
    xx.z += a.z + b.z + bb.z;
    xx.w += a.w + b.w + bb.w;
    ((float4*)x)[i] = xx;
}

// ============================================================================
// Flash attention via mma.sync (bf16 split Q,K,V,P; fp32 softmax/accum).
// 2 CTAs/SM; Q parked in smem.  Output: fp32 [ROWS][DIM].
// ============================================================================
#define ATT_SMEM 98304

__device__ __forceinline__ void attn_issue(
    int kt, int tid, uint32_t sb,
    const __nv_bfloat16* qh, const __nv_bfloat16* ql,
    size_t batch_row0, int kcol, int vcol)
{
    if (kt < 16) {
        uint32_t st = sb + (uint32_t)(kt & 1) * 32768;
        size_t rb = batch_row0 + (size_t)kt * 64;
        #pragma unroll
        for (int i = 0; i < 2; i++) {
            int idx = tid + i * 256;
            int r = idx >> 3, c = idx & 7;
            size_t rowoff = (rb + r) * QKV3;
            uint32_t so = SW128((uint32_t)(r * 128 + c * 16));
            cp16(st +         so, (const char*)(qh + rowoff + kcol) + c * 16);
            cp16(st + 8192  + so, (const char*)(ql + rowoff + kcol) + c * 16);
            cp16(st + 16384 + so, (const char*)(qh + rowoff + vcol) + c * 16);
            cp16(st + 24576 + so, (const char*)(ql + rowoff + vcol) + c * 16);
        }
    }
    CP_COMMIT();
}

__global__ __launch_bounds__(256, 2) void flash_mma_kernel(
    const __nv_bfloat16* __restrict__ qh, const __nv_bfloat16* __restrict__ ql,
    float* __restrict__ of)
{
    extern __shared__ char smem[];
    uint32_t sb = smem_u32(smem);
    int tid = threadIdx.x, wid = tid >> 5, lane = tid & 31;
    int qt = blockIdx.x;
    int b = blockIdx.y / HEADS, h = blockIdx.y % HEADS;
    int g = lane >> 2, tg = lane & 3;
    size_t batch_row0 = (size_t)b * NTOK;
    size_t qrow0 = batch_row0 + (size_t)qt * 128;
    int qcol = h * 64, kcol = DIM + h * 64, vcol = 2 * DIM + h * 64;

    #pragma unroll
    for (int i = 0; i < 4; i++) {
        int idx = tid + i * 256;
        int r = idx >> 3, c = idx & 7;
        size_t rowoff = (qrow0 + r) * QKV3 + qcol;
        uint32_t so = SW128((uint32_t)(r * 128 + c * 16));
        *(uint4*)(smem + 65536 + so) = *((const uint4*)(qh + rowoff) + c);
        *(uint4*)(smem + 81920 + so) = *((const uint4*)(ql + rowoff) + c);
    }

    uint32_t qoff[4];
    {
        uint32_t lrow = lane & 15, lh = lane >> 4;
        #pragma unroll
        for (int kf = 0; kf < 4; kf++)
            qoff[kf] = SW128((uint32_t)((wid * 16 + lrow) * 128) + kf * 32 + lh * 16);
    }
    __syncthreads();

    float m0v = -1e30f, m1v = -1e30f, l0 = 0.f, l1 = 0.f;
    float oacc[8][4] = {};
    const float scale = 0.125f;

    attn_issue(0, tid, sb, qh, ql, batch_row0, kcol, vcol);

    for (int kt = 0; kt < 16; kt++) {
        attn_issue(kt + 1, tid, sb, qh, ql, batch_row0, kcol, vcol);
        CP_WAIT1();
        __syncthreads();
        uint32_t kb = sb + (uint32_t)(kt & 1) * 32768;

        float sc[8][4] = {};
        #pragma unroll
        for (int kf = 0; kf < 4; kf++) {
            uint32_t ah[4], al[4];
            LDSM_X4(ah[0], ah[1], ah[2], ah[3], sb + 65536 + qoff[kf]);
            LDSM_X4(al[0], al[1], al[2], al[3], sb + 81920 + qoff[kf]);
            #pragma unroll
            for (int kg = 0; kg < 4; kg++) {
                uint32_t ro = (uint32_t)((kg * 16 + (lane & 15)) * 128) + kf * 32 + (lane >> 4) * 16;
                uint32_t t0, t1, t2, t3, u0, u1, u2, u3;
                LDSM_X4(t0, t1, t2, t3, kb + SW128(ro));
                LDSM_X4(u0, u1, u2, u3, kb + 8192 + SW128(ro));
                mma4(sc[2 * kg],     ah, t0, t2);
                mma4(sc[2 * kg],     ah, u0, u2);
                mma4(sc[2 * kg],     al, t0, t2);
                mma4(sc[2 * kg + 1], ah, t1, t3);
                mma4(sc[2 * kg + 1], ah, u1, u3);
                mma4(sc[2 * kg + 1], al, t1, t3);
            }
        }

        float mx0 = -1e30f, mx1 = -1e30f;
        #pragma unroll
        for (int nf = 0; nf < 8; nf++) {
            #pragma unroll
            for (int i = 0; i < 4; i++) sc[nf][i] *= scale;
            mx0 = fmaxf(mx0, fmaxf(sc[nf][0], sc[nf][1]));
            mx1 = fmaxf(mx1, fmaxf(sc[nf][2], sc[nf][3]));
        }
        mx0 = fmaxf(mx0, __shfl_xor_sync(0xffffffffu, mx0, 1));
        mx0 = fmaxf(mx0, __shfl_xor_sync(0xffffffffu, mx0, 2));
        mx1 = fmaxf(mx1, __shfl_xor_sync(0xffffffffu, mx1, 1));
        mx1 = fmaxf(mx1, __shfl_xor_sync(0xffffffffu, mx1, 2));
        float nm0 = fmaxf(m0v, mx0), nm1 = fmaxf(m1v, mx1);
        float c0 = __expf(m0v - nm0), c1 = __expf(m1v - nm1);
        l0 *= c0; l1 *= c1;
        #pragma unroll
        for (int nf = 0; nf < 8; nf++) {
            oacc[nf][0] *= c0; oacc[nf][1] *= c0;
            oacc[nf][2] *= c1; oacc[nf][3] *= c1;
        }
        m0v = nm0; m1v = nm1;
        float ps0 = 0.f, ps1 = 0.f;
        #pragma unroll
        for (int nf = 0; nf < 8; nf++) {
            sc[nf][0] = __expf(sc[nf][0] - nm0);
            sc[nf][1] = __expf(sc[nf][1] - nm0);
            sc[nf][2] = __expf(sc[nf][2] - nm1);
            sc[nf][3] = __expf(sc[nf][3] - nm1);
            ps0 += sc[nf][0] + sc[nf][1];
            ps1 += sc[nf][2] + sc[nf][3];
        }
        ps0 += __shfl_xor_sync(0xffffffffu, ps0, 1);
        ps0 += __shfl_xor_sync(0xffffffffu, ps0, 2);
        ps1 += __shfl_xor_sync(0xffffffffu, ps1, 1);
        ps1 += __shfl_xor_sync(0xffffffffu, ps1, 2);
        l0 += ps0; l1 += ps1;

        #pragma unroll
        for (int c = 0; c < 4; c++) {
            uint32_t pah[4], pal[4];
            pack_split(sc[2 * c][0],     sc[2 * c][1],     pah[0], pal[0]);
            pack_split(sc[2 * c][2],     sc[2 * c][3],     pah[1], pal[1]);
            pack_split(sc[2 * c + 1][0], sc[2 * c + 1][1], pah[2], pal[2]);
            pack_split(sc[2 * c + 1][2], sc[2 * c + 1][3], pah[3], pal[3]);
            #pragma unroll
            for (int dg = 0; dg < 4; dg++) {
                uint32_t ro = (uint32_t)((c * 16 + (lane & 15)) * 128) + dg * 32 + (lane >> 4) * 16;
                uint32_t t0, t1, t2, t3, u0, u1, u2, u3;
                LDSM_X4_T(t0, t1, t2, t3, kb + 16384 + SW128(ro));
                LDSM_X4_T(u0, u1, u2, u3, kb + 24576 + SW128(ro));
                mma4(oacc[2 * dg],     pah, t0, t1);
                mma4(oacc[2 * dg],     pah, u0, u1);
                mma4(oacc[2 * dg],     pal, t0, t1);
                mma4(oacc[2 * dg + 1], pah, t2, t3);
                mma4(oacc[2 * dg + 1], pah, u2, u3);
                mma4(oacc[2 * dg + 1], pal, t2, t3);
            }
        }
        __syncthreads();
    }

    float inv0 = 1.f / l0, inv1 = 1.f / l1;
    size_t r0 = qrow0 + wid * 16 + g;
    #pragma unroll
    for (int nf = 0; nf < 8; nf++) {
        int col = h * 64 + nf * 8 + tg * 2;
        *(float2*)(of + r0 * DIM + col) =
            make_float2(oacc[nf][0] * inv0, oacc[nf][1] * inv0);
        *(float2*)(of + (r0 + 8) * DIM + col) =
            make_float2(oacc[nf][2] * inv1, oacc[nf][3] * inv1);
    }
}

// ============================================================================
// Final transpose: x[b,n,d] -> out[b,d,n]
// ============================================================================
__global__ void transpose_out_kernel(const float* __restrict__ x,
                                     float* __restrict__ out)
{
    __shared__ float t[32][33];
    int b = blockIdx.z;
    int n0 = blockIdx.x * 32, d0 = blockIdx.y * 32;
    int tx = threadIdx.x, ty = threadIdx.y;
    for (int i = ty; i < 32; i += 8)
        t[i][tx] = x[((size_t)b * NTOK + n0 + i) * DIM + d0 + tx];
    __syncthreads();
    for (int i = ty; i < 32; i += 8)
        out[((size_t)b * DIM + d0 + i) * NTOK + n0 + tx] = t[tx][i];
}

// ============================================================================
// Host orchestration
// ============================================================================
extern "C" void kernel_launch(void* const* d_in, const int* in_sizes, int n_in,
                              void* d_out, int out_size)
{
    const float* c_f    = (const float*)d_in[0];
    const float* conv_w = (const float*)d_in[1];
    const float* conv_b = (const float*)d_in[2];
    const float* ln1_w  = (const float*)d_in[3];
    const float* ln1_b  = (const float*)d_in[4];
    const float* qkv_w  = (const float*)d_in[5];
    const float* out_w  = (const float*)d_in[6];
    const float* out_b  = (const float*)d_in[7];
    const float* ln2_w  = (const float*)d_in[8];
    const float* ln2_b  = (const float*)d_in[9];
    const float* mlp_w1 = (const float*)d_in[10];
    const float* mlp_b1 = (const float*)d_in[11];
    const float* mlp_w2 = (const float*)d_in[12];
    const float* mlp_b2 = (const float*)d_in[13];
    float* out = (float*)d_out;

    cudaFuncSetAttribute(imma_gemm_kernel,
                         cudaFuncAttributeMaxDynamicSharedMemorySize, IMMA_SMEM);
    cudaFuncSetAttribute(flash_mma_kernel,
                         cudaFuncAttributeMaxDynamicSharedMemorySize, ATT_SMEM);

    float *p_x, *p_part, *p_of, *p_hf, *p_sy, *p_so, *p_sh, *p_wscf;
    uint32_t* p_wsb;
    __nv_bfloat16 *p_qh, *p_ql;
    int8_t *p_y1, *p_y2, *p_o1, *p_o2, *p_h1, *p_h2;
    int8_t *p_qkv1, *p_qkv2, *p_out1, *p_out2, *p_m11, *p_m12, *p_m21, *p_m22;
    cudaGetSymbolAddress((void**)&p_x,    g_x);
    cudaGetSymbolAddress((void**)&p_part, g_part);
    cudaGetSymbolAddress((void**)&p_of,   g_of);
    cudaGetSymbolAddress((void**)&p_hf,   g_hf);
    cudaGetSymbolAddress((void**)&p_qh,   g_qh);
    cudaGetSymbolAddress((void**)&p_ql,   g_ql);
    cudaGetSymbolAddress((void**)&p_y1,   g_y1);
    cudaGetSymbolAddress((void**)&p_y2,   g_y2);
    cudaGetSymbolAddress((void**)&p_o1,   g_o1);
    cudaGetSymbolAddress((void**)&p_o2,   g_o2);
    cudaGetSymbolAddress((void**)&p_h1,   g_h1);
    cudaGetSymbolAddress((void**)&p_h2,   g_h2);
    cudaGetSymbolAddress((void**)&p_sy,   g_sy);
    cudaGetSymbolAddress((void**)&p_so,   g_so);
    cudaGetSymbolAddress((void**)&p_sh,   g_sh);
    cudaGetSymbolAddress((void**)&p_wsb,  g_wsb);
    cudaGetSymbolAddress((void**)&p_wscf, g_wscf);
    cudaGetSymbolAddress((void**)&p_qkv1, g_qkvq1);
    cudaGetSymbolAddress((void**)&p_qkv2, g_qkvq2);
    cudaGetSymbolAddress((void**)&p_out1, g_outq1);
    cudaGetSymbolAddress((void**)&p_out2, g_outq2);
    cudaGetSymbolAddress((void**)&p_m11,  g_m1q1);
    cudaGetSymbolAddress((void**)&p_m12,  g_m1q2);
    cudaGetSymbolAddress((void**)&p_m21,  g_m2q1);
    cudaGetSymbolAddress((void**)&p_m22,  g_m2q2);

    // Weight quantization (once per call)
    zero_scales_kernel<<<(SC_TOTAL + 255) / 256, 256>>>(p_wsb, SC_TOTAL);
    wq_max_kernel<<<DEPTH * WL_BLOCKS, dim3(32, 8)>>>(qkv_w, out_w, mlp_w1, mlp_w2, p_wsb);
    wq_finalize_kernel<<<(SC_TOTAL + 255) / 256, 256>>>(p_wsb, p_wscf, SC_TOTAL);
    wq_write_kernel<<<DEPTH * WL_BLOCKS, dim3(32, 8)>>>(
        qkv_w, out_w, mlp_w1, mlp_w2, p_wscf,
        p_qkv1, p_qkv2, p_out1, p_out2, p_m11, p_m12, p_m21, p_m22);

    embed_kernel<<<dim3(NTOK / 64, DIM / 64, BATCH), 256>>>(c_f, conv_w, conv_b, p_x);

    ln_quant_kernel<<<ROWS / 8, 256>>>(nullptr, nullptr, p_x,
                                       ln1_w, ln1_b, p_y1, p_y2, p_sy);

    for (int l = 0; l < DEPTH; l++) {
        const float* wsl = p_wscf + l * SC_PER_L;
        // QKV: K=768, N=2304 -> split bf16 out for flash
        imma_gemm_kernel<<<dim3(QKV3 / 128, ROWS / 64, 1), 256, IMMA_SMEM>>>(
            DIM, QKV3, p_y1, p_y2, p_sy,
            p_qkv1 + (size_t)l * QKV3 * DIM, p_qkv2 + (size_t)l * QKV3 * DIM,
            wsl + SOFF_QKV, nullptr, nullptr, p_qh, p_ql, 0);
        flash_mma_kernel<<<dim3(NTOK / 128, BATCH * HEADS), 256, ATT_SMEM>>>(
            p_qh, p_ql, p_of);
        act_quant_kernel<<<ROWS / 8, 256>>>(p_of, DIM / 4, p_o1, p_o2, p_so);
        // out-proj: split-K=2 -> fp32 partials; reduce fused into LN2
        imma_gemm_kernel<<<dim3(DIM / 128, ROWS / 64, 2), 256, IMMA_SMEM>>>(
            DIM, DIM, p_o1, p_o2, p_so,
            p_out1 + (size_t)l * DIM * DIM, p_out2 + (size_t)l * DIM * DIM,
            wsl + SOFF_OUT, nullptr, p_part, nullptr, nullptr, 0);
        ln_quant_kernel<<<ROWS / 8, 256>>>(p_part, out_b + l * DIM, p_x,
                                           ln2_w + l * DIM, ln2_b + l * DIM,
                                           p_y1, p_y2, p_sy);
        // MLP1: K=768, N=3072 -> fp32 h with fused bias+gelu
        imma_gemm_kernel<<<dim3(MLPD / 128, ROWS / 64, 1), 256, IMMA_SMEM>>>(
            DIM, MLPD, p_y1, p_y2, p_sy,
            p_m11 + (size_t)l * MLPD * DIM, p_m12 + (size_t)l * MLPD * DIM,
            wsl + SOFF_M1, mlp_b1 + l * MLPD, p_hf, nullptr, nullptr, 1);
        act_quant_kernel<<<ROWS / 8, 256>>>(p_hf, MLPD / 4, p_h1, p_h2, p_sh);
        // MLP2: K=3072, split-K=2 -> partials; reduce fused into next LN1
        imma_gemm_kernel<<<dim3(DIM / 128, ROWS / 64, 2), 256, IMMA_SMEM>>>(
            MLPD, DIM, p_h1, p_h2, p_sh,
            p_m21 + (size_t)l * DIM * MLPD, p_m22 + (size_t)l * DIM * MLPD,
            wsl + SOFF_M2, nullptr, p_part, nullptr, nullptr, 0);
        if (l < DEPTH - 1) {
            ln_quant_kernel<<<ROWS / 8, 256>>>(p_part, mlp_b2 + l * DIM, p_x,
                                               ln1_w + (l + 1) * DIM,
                                               ln1_b + (l + 1) * DIM,
                                               p_y1, p_y2, p_sy);
        } else {
            reduce_add_kernel<<<ROWS * DIM / 1024, 256>>>(
                p_part, mlp_b2 + l * DIM, p_x, DIM);
        }
    }

    transpose_out_kernel<<<dim3(NTOK / 32, DIM / 32, BATCH), dim3(32, 8)>>>(p_x, out);
}

// round 16
// speedup vs baseline: 2.0379x; 2.0379x over previous
#include <cuda_runtime.h>
#include <cuda_bf16.h>
#include <math.h>
#include <stdint.h>

#define DIM 768
#define NTOK 1024
#define BATCH 4
#define ROWS (BATCH * NTOK)        // 4096
#define F_DIM 256
#define HEADS 12
#define DHEAD 64
#define QKV3 (3 * DIM)             // 2304
#define MLPD 3072
#define DEPTH 8
#define LN_EPS 1e-5f

// ============================================================================
// Helpers
// ============================================================================
__device__ __forceinline__ uint32_t smem_u32(const void* p) {
    uint32_t a;
    asm("{ .reg .u64 t; cvta.to.shared.u64 t, %1; cvt.u32.u64 %0, t; }"
        : "=r"(a) : "l"(p));
    return a;
}
#define SW128(o) ((o) ^ (((o) >> 3) & 0x70))

__device__ __forceinline__ void cp16(uint32_t s, const void* g) {
    asm volatile("cp.async.cg.shared.global [%0], [%1], 16;" :: "r"(s), "l"(g));
}
#define CP_COMMIT() asm volatile("cp.async.commit_group;" ::: "memory")
#define CP_WAIT1()  asm volatile("cp.async.wait_group 1;" ::: "memory")

#define LDSM_X4(r0, r1, r2, r3, addr) \
    asm volatile("ldmatrix.sync.aligned.m8n8.x4.shared.b16 {%0,%1,%2,%3}, [%4];" \
        : "=r"(r0), "=r"(r1), "=r"(r2), "=r"(r3) : "r"(addr))
#define LDSM_X4_T(r0, r1, r2, r3, addr) \
    asm volatile("ldmatrix.sync.aligned.m8n8.x4.trans.shared.b16 {%0,%1,%2,%3}, [%4];" \
        : "=r"(r0), "=r"(r1), "=r"(r2), "=r"(r3) : "r"(addr))

__device__ __forceinline__ void mma_bf16(float* c, const uint32_t* a, const uint32_t* b) {
    asm volatile(
        "mma.sync.aligned.m16n8k16.row.col.f32.bf16.bf16.f32 "
        "{%0,%1,%2,%3}, {%4,%5,%6,%7}, {%8,%9}, {%0,%1,%2,%3};"
        : "+f"(c[0]), "+f"(c[1]), "+f"(c[2]), "+f"(c[3])
        : "r"(a[0]), "r"(a[1]), "r"(a[2]), "r"(a[3]), "r"(b[0]), "r"(b[1]));
}
__device__ __forceinline__ void mma4(float* c, const uint32_t* a, uint32_t b0, uint32_t b1) {
    uint32_t b[2] = { b0, b1 };
    mma_bf16(c, a, b);
}

__device__ __forceinline__ void split2(float v, __nv_bfloat16& h, __nv_bfloat16& l) {
    h = __float2bfloat16(v);
    l = __float2bfloat16(v - __bfloat162float(h));
}
__device__ __forceinline__ void pack_split(float a, float b, uint32_t& hi, uint32_t& lo) {
    __nv_bfloat16 ha = __float2bfloat16(a);
    __nv_bfloat16 hb = __float2bfloat16(b);
    __nv_bfloat162 H(ha, hb);
    __nv_bfloat162 L(__float2bfloat16(a - __bfloat162float(ha)),
                     __float2bfloat16(b - __bfloat162float(hb)));
    hi = *(uint32_t*)&H;
    lo = *(uint32_t*)&L;
}
__device__ __forceinline__ float gelu_f(float v) {
    return 0.5f * v * (1.0f + erff(v * 0.7071067811865475f));
}

// ============================================================================
// Scratch (device globals)
// ============================================================================
__device__ __align__(16) float g_x  [ROWS * DIM];
__device__ __align__(16) float g_part[2 * ROWS * DIM];
__device__ __align__(16) __nv_bfloat16 g_yh[ROWS * DIM],  g_yl[ROWS * DIM];
__device__ __align__(16) __nv_bfloat16 g_oh[ROWS * DIM],  g_ol[ROWS * DIM];
__device__ __align__(16) __nv_bfloat16 g_hh[ROWS * MLPD], g_hl[ROWS * MLPD];
__device__ __align__(16) __nv_bfloat16 g_qh[ROWS * QKV3], g_ql[ROWS * QKV3];
// transposed + split weights: [L][N][K]
__device__ __align__(16) __nv_bfloat16 g_qkvw_h[DEPTH * QKV3 * DIM], g_qkvw_l[DEPTH * QKV3 * DIM];
__device__ __align__(16) __nv_bfloat16 g_outw_h[DEPTH * DIM * DIM],  g_outw_l[DEPTH * DIM * DIM];
__device__ __align__(16) __nv_bfloat16 g_m1w_h [DEPTH * MLPD * DIM], g_m1w_l [DEPTH * MLPD * DIM];
__device__ __align__(16) __nv_bfloat16 g_m2w_h [DEPTH * DIM * MLPD], g_m2w_l [DEPTH * DIM * MLPD];

// ============================================================================
// Combined weight transpose + bf16 split (one launch).
// ============================================================================
#define WL_BLOCKS 6912
__global__ void wsplit_all_kernel(
    const float* __restrict__ qkv_w, const float* __restrict__ out_w,
    const float* __restrict__ m1w,   const float* __restrict__ m2w,
    __nv_bfloat16* qh, __nv_bfloat16* ql,
    __nv_bfloat16* owh, __nv_bfloat16* owl,
    __nv_bfloat16* m1h, __nv_bfloat16* m1l,
    __nv_bfloat16* m2h, __nv_bfloat16* m2l)
{
    int z = blockIdx.x;
    int l = z / WL_BLOCKS, r = z % WL_BLOCKS;
    const float* w; __nv_bfloat16 *hi, *lo; int K, N, nx, ny;
    if (r < 1728)      { w = qkv_w; hi = qh;  lo = ql;  K = DIM;  N = QKV3; nx = r % 72; ny = r / 72; }
    else if (r < 2304) { int rr = r - 1728; w = out_w; hi = owh; lo = owl; K = DIM;  N = DIM;  nx = rr % 24; ny = rr / 24; }
    else if (r < 4608) { int rr = r - 2304; w = m1w;   hi = m1h; lo = m1l; K = DIM;  N = MLPD; nx = rr % 96; ny = rr / 96; }
    else               { int rr = r - 4608; w = m2w;   hi = m2h; lo = m2l; K = MLPD; N = DIM;  nx = rr % 24; ny = rr / 24; }
    __shared__ float t[32][33];
    int n0 = nx * 32, k0 = ny * 32;
    int tx = threadIdx.x, ty = threadIdx.y;
    const float* wl = w + (size_t)l * K * N;
    for (int i = ty; i < 32; i += 8)
        t[i][tx] = wl[(size_t)(k0 + i) * N + n0 + tx];
    __syncthreads();
    size_t ob = (size_t)l * K * N;
    for (int i = ty; i < 32; i += 8) {
        float v = t[tx][i];
        __nv_bfloat16 h, lw;
        split2(v, h, lw);
        size_t o = ob + (size_t)(n0 + i) * K + k0 + tx;
        hi[o] = h; lo[o] = lw;
    }
}

// ============================================================================
// Embed GEMM with fused sine pos-embed
// ============================================================================
__device__ __forceinline__ float posval(int n, int d) {
    int r = n >> 5, c = n & 31;
    int id = (d < 384) ? d : d - 384;
    float coord = (d < 384) ? (float)(r + 1) : (float)(c + 1);
    float ang = coord * (6.283185307179586f / (32.0f + 1e-6f));
    float ex = (float)(2 * (id / 2)) * (1.0f / 384.0f);
    float p = ang / __powf(10000.0f, ex);
    return (id & 1) ? cosf(p) : sinf(p);
}

__global__ __launch_bounds__(256) void embed_kernel(
    const float* __restrict__ cf, const float* __restrict__ w,
    const float* __restrict__ bias, float* __restrict__ x)
{
    __shared__ float As[16][64];
    __shared__ float Bs[16][68];
    int b  = blockIdx.z;
    int n0 = blockIdx.x * 64, d0 = blockIdx.y * 64;
    int tid = threadIdx.x;
    int ty = tid / 16, tx = tid % 16;
    float acc[4][4] = {};
    const float* cfb = cf + (size_t)b * F_DIM * NTOK;
    for (int k0 = 0; k0 < F_DIM; k0 += 16) {
        #pragma unroll
        for (int it = 0; it < 4; it++) {
            int idx = tid + it * 256;
            As[idx >> 6][idx & 63] = cfb[(size_t)(k0 + (idx >> 6)) * NTOK + n0 + (idx & 63)];
        }
        #pragma unroll
        for (int it = 0; it < 4; it++) {
            int idx = tid + it * 256;
            Bs[idx & 15][idx >> 4] = w[(size_t)(d0 + (idx >> 4)) * F_DIM + k0 + (idx & 15)];
        }
        __syncthreads();
        #pragma unroll
        for (int kk = 0; kk < 16; kk++) {
            float a[4], bb[4];
            #pragma unroll
            for (int i = 0; i < 4; i++) a[i]  = As[kk][ty * 4 + i];
            #pragma unroll
            for (int j = 0; j < 4; j++) bb[j] = Bs[kk][tx * 4 + j];
            #pragma unroll
            for (int i = 0; i < 4; i++)
                #pragma unroll
                for (int j = 0; j < 4; j++)
                    acc[i][j] += a[i] * bb[j];
        }
        __syncthreads();
    }
    #pragma unroll
    for (int i = 0; i < 4; i++) {
        int n = n0 + ty * 4 + i;
        #pragma unroll
        for (int j = 0; j < 4; j++) {
            int d = d0 + tx * 4 + j;
            x[((size_t)b * NTOK + n) * DIM + d] = acc[i][j] + bias[d] + posval(n, d);
        }
    }
}

// ============================================================================
// LayerNorm -> split bf16 hi/lo.  Warp-per-row.
// If part != nullptr, first computes x += part0 + part1 + rbias (split-K
// reduce fused in) and writes updated x.
// ============================================================================
__global__ __launch_bounds__(256) void ln_split_kernel(
    const float* __restrict__ part, const float* __restrict__ rbias,
    float* __restrict__ x, const float* __restrict__ w,
    const float* __restrict__ bias,
    __nv_bfloat16* __restrict__ yh, __nv_bfloat16* __restrict__ yl)
{
    int warp = threadIdx.x >> 5, lane = threadIdx.x & 31;
    int row = blockIdx.x * 8 + warp;
    float4* xr = (float4*)(x + (size_t)row * DIM);
    float4 v[6];
    float s = 0.f, ss = 0.f;
    if (part) {
        const float4* p0 = (const float4*)(part + (size_t)row * DIM);
        const float4* p1 = (const float4*)(part + (size_t)(ROWS + row) * DIM);
        const float4* rb = (const float4*)rbias;
        #pragma unroll
        for (int i = 0; i < 6; i++) {
            int idx4 = lane + i * 32;
            float4 a = p0[idx4], b = p1[idx4], bb = rb[idx4];
            v[i] = xr[idx4];
            v[i].x += a.x + b.x + bb.x;
            v[i].y += a.y + b.y + bb.y;
            v[i].z += a.z + b.z + bb.z;
            v[i].w += a.w + b.w + bb.w;
            xr[idx4] = v[i];
            s  += v[i].x + v[i].y + v[i].z + v[i].w;
            ss += v[i].x * v[i].x + v[i].y * v[i].y + v[i].z * v[i].z + v[i].w * v[i].w;
        }
    } else {
        #pragma unroll
        for (int i = 0; i < 6; i++) {
            v[i] = xr[lane + i * 32];
            s  += v[i].x + v[i].y + v[i].z + v[i].w;
            ss += v[i].x * v[i].x + v[i].y * v[i].y + v[i].z * v[i].z + v[i].w * v[i].w;
        }
    }
    #pragma unroll
    for (int off = 16; off; off >>= 1) {
        s  += __shfl_xor_sync(0xffffffffu, s,  off);
        ss += __shfl_xor_sync(0xffffffffu, ss, off);
    }
    float mu  = s * (1.0f / DIM);
    float var = ss * (1.0f / DIM) - mu * mu;
    float inv = rsqrtf(var + LN_EPS);
    const float4* wv = (const float4*)w;
    const float4* bv = (const float4*)bias;
    #pragma unroll
    for (int i = 0; i < 6; i++) {
        int idx4 = lane + i * 32;
        float4 ww = wv[idx4], bb = bv[idx4];
        float y0 = (v[i].x - mu) * inv * ww.x + bb.x;
        float y1 = (v[i].y - mu) * inv * ww.y + bb.y;
        float y2 = (v[i].z - mu) * inv * ww.z + bb.z;
        float y3 = (v[i].w - mu) * inv * ww.w + bb.w;
        uint32_t h01, l01, h23, l23;
        pack_split(y0, y1, h01, l01);
        pack_split(y2, y3, h23, l23);
        uint32_t* ph = (uint32_t*)(yh + (size_t)row * DIM) + idx4 * 2;
        uint32_t* pl = (uint32_t*)(yl + (size_t)row * DIM) + idx4 * 2;
        ph[0] = h01; ph[1] = h23;
        pl[0] = l01; pl[1] = l23;
    }
}

// ============================================================================
// Tensor-core GEMM (bf16x3 split, fp32 accum), 3-stage cp.async pipeline,
// 2 CTAs/SM pinned, hoisted addressing, optional split-K via gridDim.z.
// ============================================================================
#define STG_BYTES 32768
#define MMA_SMEM  (3 * STG_BYTES)   // 98304

__global__ __launch_bounds__(256, 2) void mma_gemm_kernel(
    int K, int N,
    const __nv_bfloat16* __restrict__ Ah, const __nv_bfloat16* __restrict__ Al,
    const __nv_bfloat16* __restrict__ Bh, const __nv_bfloat16* __restrict__ Bl,
    const float* __restrict__ bias, const float* __restrict__ resid,
    float* __restrict__ outf,
    __nv_bfloat16* __restrict__ oh, __nv_bfloat16* __restrict__ ol,
    int gelu)
{
    extern __shared__ char smem[];
    uint32_t sbase = smem_u32(smem);
    int tid = threadIdx.x, wid = tid >> 5, lane = tid & 31;
    int n0 = blockIdx.x * 128, m0 = blockIdx.y * 128;

    // split-K range
    int nch_tot = K / 32;
    int per = nch_tot / gridDim.z;
    int ch_begin = blockIdx.z * per;
    int chend = ch_begin + per;

    // hoisted cp.async addressing
    int r_cp = tid >> 2, c_cp = tid & 3;
    uint32_t soff0 = SW128((uint32_t)(r_cp * 64 + c_cp * 16));
    uint32_t soff1 = SW128((uint32_t)((r_cp + 64) * 64 + c_cp * 16));
    size_t goff0 = ((size_t)r_cp * K + c_cp * 8) * 2;
    size_t goff1 = ((size_t)(r_cp + 64) * K + c_cp * 8) * 2;
    const char* pAh = (const char*)(Ah + (size_t)m0 * K);
    const char* pAl = (const char*)(Al + (size_t)m0 * K);
    const char* pBh = (const char*)(Bh + (size_t)n0 * K);
    const char* pBl = (const char*)(Bl + (size_t)n0 * K);

#define ISSUE(CH) do { \
    if ((CH) < chend) { \
        uint32_t sb0 = sbase + (uint32_t)((CH) % 3) * STG_BYTES; \
        size_t kb = (size_t)(CH) * 64; \
        cp16(sb0 +          soff0, pAh + kb + goff0); \
        cp16(sb0 +          soff1, pAh + kb + goff1); \
        cp16(sb0 + 8192  +  soff0, pAl + kb + goff0); \
        cp16(sb0 + 8192  +  soff1, pAl + kb + goff1); \
        cp16(sb0 + 16384 +  soff0, pBh + kb + goff0); \
        cp16(sb0 + 16384 +  soff1, pBh + kb + goff1); \
        cp16(sb0 + 24576 +  soff0, pBl + kb + goff0); \
        cp16(sb0 + 24576 +  soff1, pBl + kb + goff1); \
    } \
    CP_COMMIT(); } while (0)

    int wm = wid >> 2, wn = wid & 3;
    uint32_t lrow = lane & 15, lhalf = lane >> 4;

    // hoisted ldmatrix swizzled offsets (lo tile = hi addr + 8192)
    uint32_t aoff[2][4], boff[2][2];
    #pragma unroll
    for (int ks = 0; ks < 2; ks++) {
        uint32_t koff = (uint32_t)(ks * 2 + lhalf) * 16;
        #pragma unroll
        for (int mf = 0; mf < 4; mf++)
            aoff[ks][mf] = SW128((uint32_t)((wm * 64 + mf * 16 + lrow) * 64) + koff);
        #pragma unroll
        for (int nf2 = 0; nf2 < 2; nf2++)
            boff[ks][nf2] = SW128((uint32_t)((wn * 32 + nf2 * 16 + lrow) * 64) + koff);
    }

    float acc[4][4][4] = {};

    ISSUE(ch_begin);
    ISSUE(ch_begin + 1);

    for (int ch = ch_begin; ch < chend; ch++) {
        CP_WAIT1();
        __syncthreads();
        ISSUE(ch + 2);
        uint32_t st = sbase + (uint32_t)(ch % 3) * STG_BYTES;
        #pragma unroll
        for (int ks = 0; ks < 2; ks++) {
            uint32_t ah[4][4], al[4][4], bh[4][2], bl[4][2];
            #pragma unroll
            for (int mf = 0; mf < 4; mf++) {
                uint32_t a0 = st + aoff[ks][mf];
                LDSM_X4(ah[mf][0], ah[mf][1], ah[mf][2], ah[mf][3], a0);
                LDSM_X4(al[mf][0], al[mf][1], al[mf][2], al[mf][3], a0 + 8192);
            }
            #pragma unroll
            for (int nf2 = 0; nf2 < 2; nf2++) {
                uint32_t b0 = st + 16384 + boff[ks][nf2];
                uint32_t t0, t1, t2, t3;
                LDSM_X4(t0, t1, t2, t3, b0);
                bh[nf2 * 2][0] = t0; bh[nf2 * 2 + 1][0] = t1;
                bh[nf2 * 2][1] = t2; bh[nf2 * 2 + 1][1] = t3;
                LDSM_X4(t0, t1, t2, t3, b0 + 8192);
                bl[nf2 * 2][0] = t0; bl[nf2 * 2 + 1][0] = t1;
                bl[nf2 * 2][1] = t2; bl[nf2 * 2 + 1][1] = t3;
            }
            #pragma unroll
            for (int mf = 0; mf < 4; mf++) {
                #pragma unroll
                for (int nf = 0; nf < 4; nf++) {
                    mma_bf16(acc[mf][nf], ah[mf], bh[nf]);
                    mma_bf16(acc[mf][nf], ah[mf], bl[nf]);
                    mma_bf16(acc[mf][nf], al[mf], bh[nf]);
                }
            }
        }
    }
#undef ISSUE

    // Epilogue
    float* myout = outf ? (outf + (size_t)blockIdx.z * ((size_t)ROWS * N)) : (float*)0;
    int g = lane >> 2, tg = lane & 3;
    #pragma unroll
    for (int mf = 0; mf < 4; mf++) {
        #pragma unroll
        for (int nf = 0; nf < 4; nf++) {
            int col = n0 + wn * 32 + nf * 8 + tg * 2;
            float bv0 = bias ? __ldg(bias + col)     : 0.f;
            float bv1 = bias ? __ldg(bias + col + 1) : 0.f;
            #pragma unroll
            for (int half = 0; half < 2; half++) {
                int row = m0 + wm * 64 + mf * 16 + g + half * 8;
                float v0 = acc[mf][nf][half * 2 + 0] + bv0;
                float v1 = acc[mf][nf][half * 2 + 1] + bv1;
                if (gelu) { v0 = gelu_f(v0); v1 = gelu_f(v1); }
                size_t gb = (size_t)row * N + col;
                if (resid) {
                    float2 rr = *(const float2*)(resid + gb);
                    v0 += rr.x; v1 += rr.y;
                }
                if (myout) {
                    *(float2*)(myout + gb) = make_float2(v0, v1);
                } else {
                    __nv_bfloat16 h0, l0, h1, l1;
                    split2(v0, h0, l0); split2(v1, h1, l1);
                    *(__nv_bfloat162*)(oh + gb) = __nv_bfloat162(h0, h1);
                    *(__nv_bfloat162*)(ol + gb) = __nv_bfloat162(l0, l1);
                }
            }
        }
    }
}

// ============================================================================
// Flash attention via mma.sync (bf16 split Q,K,V,P; fp32 softmax/accum).
// 2 CTAs/SM.  Q parked in dedicated smem; fragments re-loaded per K-tile.
// ============================================================================
#define ATT_SMEM 98304

__device__ __forceinline__ void attn_issue(
    int kt, int tid, uint32_t sb,
    const __nv_bfloat16* qh, const __nv_bfloat16* ql,
    size_t batch_row0, int kcol, int vcol)
{
    if (kt < 16) {
        uint32_t st = sb + (uint32_t)(kt & 1) * 32768;
        size_t rb = batch_row0 + (size_t)kt * 64;
        #pragma unroll
        for (int i = 0; i < 2; i++) {
            int idx = tid + i * 256;
            int r = idx >> 3, c = idx & 7;
            size_t rowoff = (rb + r) * QKV3;
            uint32_t so = SW128((uint32_t)(r * 128 + c * 16));
            cp16(st +         so, (const char*)(qh + rowoff + kcol) + c * 16);
            cp16(st + 8192  + so, (const char*)(ql + rowoff + kcol) + c * 16);
            cp16(st + 16384 + so, (const char*)(qh + rowoff + vcol) + c * 16);
            cp16(st + 24576 + so, (const char*)(ql + rowoff + vcol) + c * 16);
        }
    }
    CP_COMMIT();
}

__global__ __launch_bounds__(256, 2) void flash_mma_kernel(
    const __nv_bfloat16* __restrict__ qh, const __nv_bfloat16* __restrict__ ql,
    __nv_bfloat16* __restrict__ oh, __nv_bfloat16* __restrict__ ol)
{
    extern __shared__ char smem[];
    uint32_t sb = smem_u32(smem);
    int tid = threadIdx.x, wid = tid >> 5, lane = tid & 31;
    int qt = blockIdx.x;
    int b = blockIdx.y / HEADS, h = blockIdx.y % HEADS;
    int g = lane >> 2, tg = lane & 3;
    size_t batch_row0 = (size_t)b * NTOK;
    size_t qrow0 = batch_row0 + (size_t)qt * 128;
    int qcol = h * 64, kcol = DIM + h * 64, vcol = 2 * DIM + h * 64;

    // Stage Q into dedicated region [64KB..96KB): hi at +65536, lo at +81920
    #pragma unroll
    for (int i = 0; i < 4; i++) {
        int idx = tid + i * 256;
        int r = idx >> 3, c = idx & 7;
        size_t rowoff = (qrow0 + r) * QKV3 + qcol;
        uint32_t so = SW128((uint32_t)(r * 128 + c * 16));
        *(uint4*)(smem + 65536 + so) = *((const uint4*)(qh + rowoff) + c);
        *(uint4*)(smem + 81920 + so) = *((const uint4*)(ql + rowoff) + c);
    }

    uint32_t qoff[4];
    {
        uint32_t lrow = lane & 15, lh = lane >> 4;
        #pragma unroll
        for (int kf = 0; kf < 4; kf++)
            qoff[kf] = SW128((uint32_t)((wid * 16 + lrow) * 128) + kf * 32 + lh * 16);
    }
    __syncthreads();

    float m0v = -1e30f, m1v = -1e30f, l0 = 0.f, l1 = 0.f;
    float oacc[8][4] = {};
    const float scale = 0.125f;

    attn_issue(0, tid, sb, qh, ql, batch_row0, kcol, vcol);

    for (int kt = 0; kt < 16; kt++) {
        attn_issue(kt + 1, tid, sb, qh, ql, batch_row0, kcol, vcol);
        CP_WAIT1();
        __syncthreads();
        uint32_t kb = sb + (uint32_t)(kt & 1) * 32768;

        float sc[8][4] = {};
        #pragma unroll
        for (int kf = 0; kf < 4; kf++) {
            uint32_t ah[4], al[4];
            LDSM_X4(ah[0], ah[1], ah[2], ah[3], sb + 65536 + qoff[kf]);
            LDSM_X4(al[0], al[1], al[2], al[3], sb + 81920 + qoff[kf]);
            #pragma unroll
            for (int kg = 0; kg < 4; kg++) {
                uint32_t ro = (uint32_t)((kg * 16 + (lane & 15)) * 128) + kf * 32 + (lane >> 4) * 16;
                uint32_t t0, t1, t2, t3, u0, u1, u2, u3;
                LDSM_X4(t0, t1, t2, t3, kb + SW128(ro));
                LDSM_X4(u0, u1, u2, u3, kb + 8192 + SW128(ro));
                mma4(sc[2 * kg],     ah, t0, t2);
                mma4(sc[2 * kg],     ah, u0, u2);
                mma4(sc[2 * kg],     al, t0, t2);
                mma4(sc[2 * kg + 1], ah, t1, t3);
                mma4(sc[2 * kg + 1], ah, u1, u3);
                mma4(sc[2 * kg + 1], al, t1, t3);
            }
        }

        float mx0 = -1e30f, mx1 = -1e30f;
        #pragma unroll
        for (int nf = 0; nf < 8; nf++) {
            #pragma unroll
            for (int i = 0; i < 4; i++) sc[nf][i] *= scale;
            mx0 = fmaxf(mx0, fmaxf(sc[nf][0], sc[nf][1]));
            mx1 = fmaxf(mx1, fmaxf(sc[nf][2], sc[nf][3]));
        }
        mx0 = fmaxf(mx0, __shfl_xor_sync(0xffffffffu, mx0, 1));
        mx0 = fmaxf(mx0, __shfl_xor_sync(0xffffffffu, mx0, 2));
        mx1 = fmaxf(mx1, __shfl_xor_sync(0xffffffffu, mx1, 1));
        mx1 = fmaxf(mx1, __shfl_xor_sync(0xffffffffu, mx1, 2));
        float nm0 = fmaxf(m0v, mx0), nm1 = fmaxf(m1v, mx1);
        float c0 = __expf(m0v - nm0), c1 = __expf(m1v - nm1);
        l0 *= c0; l1 *= c1;
        #pragma unroll
        for (int nf = 0; nf < 8; nf++) {
            oacc[nf][0] *= c0; oacc[nf][1] *= c0;
            oacc[nf][2] *= c1; oacc[nf][3] *= c1;
        }
        m0v = nm0; m1v = nm1;
        float ps0 = 0.f, ps1 = 0.f;
        #pragma unroll
        for (int nf = 0; nf < 8; nf++) {
            sc[nf][0] = __expf(sc[nf][0] - nm0);
            sc[nf][1] = __expf(sc[nf][1] - nm0);
            sc[nf][2] = __expf(sc[nf][2] - nm1);
            sc[nf][3] = __expf(sc[nf][3] - nm1);
            ps0 += sc[nf][0] + sc[nf][1];
            ps1 += sc[nf][2] + sc[nf][3];
        }
        ps0 += __shfl_xor_sync(0xffffffffu, ps0, 1);
        ps0 += __shfl_xor_sync(0xffffffffu, ps0, 2);
        ps1 += __shfl_xor_sync(0xffffffffu, ps1, 1);
        ps1 += __shfl_xor_sync(0xffffffffu, ps1, 2);
        l0 += ps0; l1 += ps1;

        #pragma unroll
        for (int c = 0; c < 4; c++) {
            uint32_t pah[4], pal[4];
            pack_split(sc[2 * c][0],     sc[2 * c][1],     pah[0], pal[0]);
            pack_split(sc[2 * c][2],     sc[2 * c][3],     pah[1], pal[1]);
            pack_split(sc[2 * c + 1][0], sc[2 * c + 1][1], pah[2], pal[2]);
            pack_split(sc[2 * c + 1][2], sc[2 * c + 1][3], pah[3], pal[3]);
            #pragma unroll
            for (int dg = 0; dg < 4; dg++) {
                uint32_t ro = (uint32_t)((c * 16 + (lane & 15)) * 128) + dg * 32 + (lane >> 4) * 16;
                uint32_t t0, t1, t2, t3, u0, u1, u2, u3;
                LDSM_X4_T(t0, t1, t2, t3, kb + 16384 + SW128(ro));
                LDSM_X4_T(u0, u1, u2, u3, kb + 24576 + SW128(ro));
                mma4(oacc[2 * dg],     pah, t0, t1);
                mma4(oacc[2 * dg],     pah, u0, u1);
                mma4(oacc[2 * dg],     pal, t0, t1);
                mma4(oacc[2 * dg + 1], pah, t2, t3);
                mma4(oacc[2 * dg + 1], pah, u2, u3);
                mma4(oacc[2 * dg + 1], pal, t2, t3);
            }
        }
        __syncthreads();
    }

    float inv0 = 1.f / l0, inv1 = 1.f / l1;
    size_t r0 = qrow0 + wid * 16 + g;
    #pragma unroll
    for (int nf = 0; nf < 8; nf++) {
        int col = h * 64 + nf * 8 + tg * 2;
        float v0 = oacc[nf][0] * inv0, v1 = oacc[nf][1] * inv0;
        float v2 = oacc[nf][2] * inv1, v3 = oacc[nf][3] * inv1;
        __nv_bfloat16 h0, lo0, h1, lo1;
        split2(v0, h0, lo0); split2(v1, h1, lo1);
        *(__nv_bfloat162*)(oh + r0 * DIM + col) = __nv_bfloat162(h0, h1);
        *(__nv_bfloat162*)(ol + r0 * DIM + col) = __nv_bfloat162(lo0, lo1);
        split2(v2, h0, lo0); split2(v3, h1, lo1);
        *(__nv_bfloat162*)(oh + (r0 + 8) * DIM + col) = __nv_bfloat162(h0, h1);
        *(__nv_bfloat162*)(ol + (r0 + 8) * DIM + col) = __nv_bfloat162(lo0, lo1);
    }
}

// ============================================================================
// Final transpose with fused split-K reduce:
// out[b,d,n] = x[b,n,d] + part0[b,n,d] + part1[b,n,d] + bias[d]
// ============================================================================
__global__ void transpose_out_kernel(const float* __restrict__ x,
                                     const float* __restrict__ part,
                                     const float* __restrict__ bias,
                                     float* __restrict__ out)
{
    __shared__ float t[32][33];
    int b = blockIdx.z;
    int n0 = blockIdx.x * 32, d0 = blockIdx.y * 32;
    int tx = threadIdx.x, ty = threadIdx.y;
    float bv = bias[d0 + tx];
    for (int i = ty; i < 32; i += 8) {
        size_t idx = ((size_t)b * NTOK + n0 + i) * DIM + d0 + tx;
        t[i][tx] = x[idx] + part[idx] + part[(size_t)ROWS * DIM + idx] + bv;
    }
    __syncthreads();
    for (int i = ty; i < 32; i += 8)
        out[((size_t)b * DIM + d0 + i) * NTOK + n0 + tx] = t[tx][i];
}

// ============================================================================
// Host orchestration
// ============================================================================
extern "C" void kernel_launch(void* const* d_in, const int* in_sizes, int n_in,
                              void* d_out, int out_size)
{
    const float* c_f    = (const float*)d_in[0];
    const float* conv_w = (const float*)d_in[1];
    const float* conv_b = (const float*)d_in[2];
    const float* ln1_w  = (const float*)d_in[3];
    const float* ln1_b  = (const float*)d_in[4];
    const float* qkv_w  = (const float*)d_in[5];
    const float* out_w  = (const float*)d_in[6];
    const float* out_b  = (const float*)d_in[7];
    const float* ln2_w  = (const float*)d_in[8];
    const float* ln2_b  = (const float*)d_in[9];
    const float* mlp_w1 = (const float*)d_in[10];
    const float* mlp_b1 = (const float*)d_in[11];
    const float* mlp_w2 = (const float*)d_in[12];
    const float* mlp_b2 = (const float*)d_in[13];
    float* out = (float*)d_out;

    cudaFuncSetAttribute(mma_gemm_kernel,
                         cudaFuncAttributeMaxDynamicSharedMemorySize, MMA_SMEM);
    cudaFuncSetAttribute(flash_mma_kernel,
                         cudaFuncAttributeMaxDynamicSharedMemorySize, ATT_SMEM);

    float *p_x, *p_part;
    __nv_bfloat16 *p_yh, *p_yl, *p_oh, *p_ol, *p_hh, *p_hl, *p_qh, *p_ql;
    __nv_bfloat16 *p_qwh, *p_qwl, *p_owh, *p_owl, *p_m1h, *p_m1l, *p_m2h, *p_m2l;
    cudaGetSymbolAddress((void**)&p_x,    g_x);
    cudaGetSymbolAddress((void**)&p_part, g_part);
    cudaGetSymbolAddress((void**)&p_yh,  g_yh);
    cudaGetSymbolAddress((void**)&p_yl,  g_yl);
    cudaGetSymbolAddress((void**)&p_oh,  g_oh);
    cudaGetSymbolAddress((void**)&p_ol,  g_ol);
    cudaGetSymbolAddress((void**)&p_hh,  g_hh);
    cudaGetSymbolAddress((void**)&p_hl,  g_hl);
    cudaGetSymbolAddress((void**)&p_qh,  g_qh);
    cudaGetSymbolAddress((void**)&p_ql,  g_ql);
    cudaGetSymbolAddress((void**)&p_qwh, g_qkvw_h);
    cudaGetSymbolAddress((void**)&p_qwl, g_qkvw_l);
    cudaGetSymbolAddress((void**)&p_owh, g_outw_h);
    cudaGetSymbolAddress((void**)&p_owl, g_outw_l);
    cudaGetSymbolAddress((void**)&p_m1h, g_m1w_h);
    cudaGetSymbolAddress((void**)&p_m1l, g_m1w_l);
    cudaGetSymbolAddress((void**)&p_m2h, g_m2w_h);
    cudaGetSymbolAddress((void**)&p_m2l, g_m2w_l);

    wsplit_all_kernel<<<DEPTH * WL_BLOCKS, dim3(32, 8)>>>(
        qkv_w, out_w, mlp_w1, mlp_w2,
        p_qwh, p_qwl, p_owh, p_owl, p_m1h, p_m1l, p_m2h, p_m2l);

    embed_kernel<<<dim3(NTOK / 64, DIM / 64, BATCH), 256>>>(c_f, conv_w, conv_b, p_x);

    // layer 0 LN1 (no pending split-K reduce)
    ln_split_kernel<<<ROWS / 8, 256>>>(nullptr, nullptr, p_x,
                                       ln1_w, ln1_b, p_yh, p_yl);

    for (int l = 0; l < DEPTH; l++) {
        mma_gemm_kernel<<<dim3(QKV3 / 128, ROWS / 128, 1), 256, MMA_SMEM>>>(
            DIM, QKV3, p_yh, p_yl,
            p_qwh + (size_t)l * QKV3 * DIM, p_qwl + (size_t)l * QKV3 * DIM,
            nullptr, nullptr, nullptr, p_qh, p_ql, 0);
        flash_mma_kernel<<<dim3(NTOK / 128, BATCH * HEADS), 256, ATT_SMEM>>>(
            p_qh, p_ql, p_oh, p_ol);
        // attn out-proj: split-K=2 -> partials; reduce fused into LN2
        mma_gemm_kernel<<<dim3(DIM / 128, ROWS / 128, 2), 256, MMA_SMEM>>>(
            DIM, DIM, p_oh, p_ol,
            p_owh + (size_t)l * DIM * DIM, p_owl + (size_t)l * DIM * DIM,
            nullptr, nullptr, p_part, nullptr, nullptr, 0);
        ln_split_kernel<<<ROWS / 8, 256>>>(p_part, out_b + l * DIM, p_x,
                                           ln2_w + l * DIM, ln2_b + l * DIM,
                                           p_yh, p_yl);
        mma_gemm_kernel<<<dim3(MLPD / 128, ROWS / 128, 1), 256, MMA_SMEM>>>(
            DIM, MLPD, p_yh, p_yl,
            p_m1h + (size_t)l * MLPD * DIM, p_m1l + (size_t)l * MLPD * DIM,
            mlp_b1 + l * MLPD, nullptr, nullptr, p_hh, p_hl, 1);
        // mlp2: split-K=2 -> partials; reduce fused into next layer's LN1
        // (last layer: reduce fused into the final transpose)
        mma_gemm_kernel<<<dim3(DIM / 128, ROWS / 128, 2), 256, MMA_SMEM>>>(
            MLPD, DIM, p_hh, p_hl,
            p_m2h + (size_t)l * DIM * MLPD, p_m2l + (size_t)l * DIM * MLPD,
            nullptr, nullptr, p_part, nullptr, nullptr, 0);
        if (l < DEPTH - 1) {
            ln_split_kernel<<<ROWS / 8, 256>>>(p_part, mlp_b2 + l * DIM, p_x,
                                               ln1_w + (l + 1) * DIM,
                                               ln1_b + (l + 1) * DIM,
                                               p_yh, p_yl);
        }
    }

    transpose_out_kernel<<<dim3(NTOK / 32, DIM / 32, BATCH), dim3(32, 8)>>>(
        p_x, p_part, mlp_b2 + (DEPTH - 1) * DIM, out);
}

// round 17
// speedup vs baseline: 2.1046x; 1.0328x over previous
#include <cuda_runtime.h>
#include <cuda_bf16.h>
#include <math.h>
#include <stdint.h>

#define DIM 768
#define NTOK 1024
#define BATCH 4
#define ROWS (BATCH * NTOK)        // 4096
#define F_DIM 256
#define HEADS 12
#define DHEAD 64
#define QKV3 (3 * DIM)             // 2304
#define MLPD 3072
#define DEPTH 8
#define LN_EPS 1e-5f

// ============================================================================
// Helpers
// ============================================================================
__device__ __forceinline__ uint32_t smem_u32(const void* p) {
    uint32_t a;
    asm("{ .reg .u64 t; cvta.to.shared.u64 t, %1; cvt.u32.u64 %0, t; }"
        : "=r"(a) : "l"(p));
    return a;
}
#define SW128(o) ((o) ^ (((o) >> 3) & 0x70))

__device__ __forceinline__ void cp16(uint32_t s, const void* g) {
    asm volatile("cp.async.cg.shared.global [%0], [%1], 16;" :: "r"(s), "l"(g));
}
#define CP_COMMIT() asm volatile("cp.async.commit_group;" ::: "memory")
#define CP_WAIT1()  asm volatile("cp.async.wait_group 1;" ::: "memory")

#define LDSM_X4(r0, r1, r2, r3, addr) \
    asm volatile("ldmatrix.sync.aligned.m8n8.x4.shared.b16 {%0,%1,%2,%3}, [%4];" \
        : "=r"(r0), "=r"(r1), "=r"(r2), "=r"(r3) : "r"(addr))
#define LDSM_X4_T(r0, r1, r2, r3, addr) \
    asm volatile("ldmatrix.sync.aligned.m8n8.x4.trans.shared.b16 {%0,%1,%2,%3}, [%4];" \
        : "=r"(r0), "=r"(r1), "=r"(r2), "=r"(r3) : "r"(addr))

__device__ __forceinline__ void mma_bf16(float* c, const uint32_t* a, const uint32_t* b) {
    asm volatile(
        "mma.sync.aligned.m16n8k16.row.col.f32.bf16.bf16.f32 "
        "{%0,%1,%2,%3}, {%4,%5,%6,%7}, {%8,%9}, {%0,%1,%2,%3};"
        : "+f"(c[0]), "+f"(c[1]), "+f"(c[2]), "+f"(c[3])
        : "r"(a[0]), "r"(a[1]), "r"(a[2]), "r"(a[3]), "r"(b[0]), "r"(b[1]));
}
__device__ __forceinline__ void mma4(float* c, const uint32_t* a, uint32_t b0, uint32_t b1) {
    uint32_t b[2] = { b0, b1 };
    mma_bf16(c, a, b);
}

__device__ __forceinline__ void split2(float v, __nv_bfloat16& h, __nv_bfloat16& l) {
    h = __float2bfloat16(v);
    l = __float2bfloat16(v - __bfloat162float(h));
}
__device__ __forceinline__ void pack_split(float a, float b, uint32_t& hi, uint32_t& lo) {
    __nv_bfloat16 ha = __float2bfloat16(a);
    __nv_bfloat16 hb = __float2bfloat16(b);
    __nv_bfloat162 H(ha, hb);
    __nv_bfloat162 L(__float2bfloat16(a - __bfloat162float(ha)),
                     __float2bfloat16(b - __bfloat162float(hb)));
    hi = *(uint32_t*)&H;
    lo = *(uint32_t*)&L;
}
__device__ __forceinline__ float gelu_f(float v) {
    return 0.5f * v * (1.0f + erff(v * 0.7071067811865475f));
}

// ============================================================================
// Scratch (device globals)
// ============================================================================
__device__ __align__(16) float g_x  [ROWS * DIM];
__device__ __align__(16) float g_part[3 * ROWS * DIM];
__device__ __align__(16) __nv_bfloat16 g_yh[ROWS * DIM],  g_yl[ROWS * DIM];
__device__ __align__(16) __nv_bfloat16 g_oh[ROWS * DIM],  g_ol[ROWS * DIM];
__device__ __align__(16) __nv_bfloat16 g_hh[ROWS * MLPD], g_hl[ROWS * MLPD];
__device__ __align__(16) __nv_bfloat16 g_qh[ROWS * QKV3], g_ql[ROWS * QKV3];
// transposed + split weights: [L][N][K]
__device__ __align__(16) __nv_bfloat16 g_qkvw_h[DEPTH * QKV3 * DIM], g_qkvw_l[DEPTH * QKV3 * DIM];
__device__ __align__(16) __nv_bfloat16 g_outw_h[DEPTH * DIM * DIM],  g_outw_l[DEPTH * DIM * DIM];
__device__ __align__(16) __nv_bfloat16 g_m1w_h [DEPTH * MLPD * DIM], g_m1w_l [DEPTH * MLPD * DIM];
__device__ __align__(16) __nv_bfloat16 g_m2w_h [DEPTH * DIM * MLPD], g_m2w_l [DEPTH * DIM * MLPD];

// ============================================================================
// Combined weight transpose + bf16 split (one launch).
// ============================================================================
#define WL_BLOCKS 6912
__global__ void wsplit_all_kernel(
    const float* __restrict__ qkv_w, const float* __restrict__ out_w,
    const float* __restrict__ m1w,   const float* __restrict__ m2w,
    __nv_bfloat16* qh, __nv_bfloat16* ql,
    __nv_bfloat16* owh, __nv_bfloat16* owl,
    __nv_bfloat16* m1h, __nv_bfloat16* m1l,
    __nv_bfloat16* m2h, __nv_bfloat16* m2l)
{
    int z = blockIdx.x;
    int l = z / WL_BLOCKS, r = z % WL_BLOCKS;
    const float* w; __nv_bfloat16 *hi, *lo; int K, N, nx, ny;
    if (r < 1728)      { w = qkv_w; hi = qh;  lo = ql;  K = DIM;  N = QKV3; nx = r % 72; ny = r / 72; }
    else if (r < 2304) { int rr = r - 1728; w = out_w; hi = owh; lo = owl; K = DIM;  N = DIM;  nx = rr % 24; ny = rr / 24; }
    else if (r < 4608) { int rr = r - 2304; w = m1w;   hi = m1h; lo = m1l; K = DIM;  N = MLPD; nx = rr % 96; ny = rr / 96; }
    else               { int rr = r - 4608; w = m2w;   hi = m2h; lo = m2l; K = MLPD; N = DIM;  nx = rr % 24; ny = rr / 24; }
    __shared__ float t[32][33];
    int n0 = nx * 32, k0 = ny * 32;
    int tx = threadIdx.x, ty = threadIdx.y;
    const float* wl = w + (size_t)l * K * N;
    for (int i = ty; i < 32; i += 8)
        t[i][tx] = wl[(size_t)(k0 + i) * N + n0 + tx];
    __syncthreads();
    size_t ob = (size_t)l * K * N;
    for (int i = ty; i < 32; i += 8) {
        float v = t[tx][i];
        __nv_bfloat16 h, lw;
        split2(v, h, lw);
        size_t o = ob + (size_t)(n0 + i) * K + k0 + tx;
        hi[o] = h; lo[o] = lw;
    }
}

// ============================================================================
// Embed GEMM with fused sine pos-embed
// ============================================================================
__device__ __forceinline__ float posval(int n, int d) {
    int r = n >> 5, c = n & 31;
    int id = (d < 384) ? d : d - 384;
    float coord = (d < 384) ? (float)(r + 1) : (float)(c + 1);
    float ang = coord * (6.283185307179586f / (32.0f + 1e-6f));
    float ex = (float)(2 * (id / 2)) * (1.0f / 384.0f);
    float p = ang / __powf(10000.0f, ex);
    return (id & 1) ? cosf(p) : sinf(p);
}

__global__ __launch_bounds__(256) void embed_kernel(
    const float* __restrict__ cf, const float* __restrict__ w,
    const float* __restrict__ bias, float* __restrict__ x)
{
    __shared__ float As[16][64];
    __shared__ float Bs[16][68];
    int b  = blockIdx.z;
    int n0 = blockIdx.x * 64, d0 = blockIdx.y * 64;
    int tid = threadIdx.x;
    int ty = tid / 16, tx = tid % 16;
    float acc[4][4] = {};
    const float* cfb = cf + (size_t)b * F_DIM * NTOK;
    for (int k0 = 0; k0 < F_DIM; k0 += 16) {
        #pragma unroll
        for (int it = 0; it < 4; it++) {
            int idx = tid + it * 256;
            As[idx >> 6][idx & 63] = cfb[(size_t)(k0 + (idx >> 6)) * NTOK + n0 + (idx & 63)];
        }
        #pragma unroll
        for (int it = 0; it < 4; it++) {
            int idx = tid + it * 256;
            Bs[idx & 15][idx >> 4] = w[(size_t)(d0 + (idx >> 4)) * F_DIM + k0 + (idx & 15)];
        }
        __syncthreads();
        #pragma unroll
        for (int kk = 0; kk < 16; kk++) {
            float a[4], bb[4];
            #pragma unroll
            for (int i = 0; i < 4; i++) a[i]  = As[kk][ty * 4 + i];
            #pragma unroll
            for (int j = 0; j < 4; j++) bb[j] = Bs[kk][tx * 4 + j];
            #pragma unroll
            for (int i = 0; i < 4; i++)
                #pragma unroll
                for (int j = 0; j < 4; j++)
                    acc[i][j] += a[i] * bb[j];
        }
        __syncthreads();
    }
    #pragma unroll
    for (int i = 0; i < 4; i++) {
        int n = n0 + ty * 4 + i;
        #pragma unroll
        for (int j = 0; j < 4; j++) {
            int d = d0 + tx * 4 + j;
            x[((size_t)b * NTOK + n) * DIM + d] = acc[i][j] + bias[d] + posval(n, d);
        }
    }
}

// ============================================================================
// LayerNorm -> split bf16 hi/lo.  Warp-per-row.
// If part != nullptr, first computes x += part0 + part1 + part2 + rbias
// (split-K=3 reduce fused in) and writes updated x.
// ============================================================================
__global__ __launch_bounds__(256) void ln_split_kernel(
    const float* __restrict__ part, const float* __restrict__ rbias,
    float* __restrict__ x, const float* __restrict__ w,
    const float* __restrict__ bias,
    __nv_bfloat16* __restrict__ yh, __nv_bfloat16* __restrict__ yl)
{
    int warp = threadIdx.x >> 5, lane = threadIdx.x & 31;
    int row = blockIdx.x * 8 + warp;
    float4* xr = (float4*)(x + (size_t)row * DIM);
    float4 v[6];
    float s = 0.f, ss = 0.f;
    if (part) {
        const float4* p0 = (const float4*)(part + (size_t)row * DIM);
        const float4* p1 = (const float4*)(part + (size_t)(ROWS + row) * DIM);
        const float4* p2 = (const float4*)(part + (size_t)(2 * ROWS + row) * DIM);
        const float4* rb = (const float4*)rbias;
        #pragma unroll
        for (int i = 0; i < 6; i++) {
            int idx4 = lane + i * 32;
            float4 a = p0[idx4], b = p1[idx4], c = p2[idx4], bb = rb[idx4];
            v[i] = xr[idx4];
            v[i].x += a.x + b.x + c.x + bb.x;
            v[i].y += a.y + b.y + c.y + bb.y;
            v[i].z += a.z + b.z + c.z + bb.z;
            v[i].w += a.w + b.w + c.w + bb.w;
            xr[idx4] = v[i];
            s  += v[i].x + v[i].y + v[i].z + v[i].w;
            ss += v[i].x * v[i].x + v[i].y * v[i].y + v[i].z * v[i].z + v[i].w * v[i].w;
        }
    } else {
        #pragma unroll
        for (int i = 0; i < 6; i++) {
            v[i] = xr[lane + i * 32];
            s  += v[i].x + v[i].y + v[i].z + v[i].w;
            ss += v[i].x * v[i].x + v[i].y * v[i].y + v[i].z * v[i].z + v[i].w * v[i].w;
        }
    }
    #pragma unroll
    for (int off = 16; off; off >>= 1) {
        s  += __shfl_xor_sync(0xffffffffu, s,  off);
        ss += __shfl_xor_sync(0xffffffffu, ss, off);
    }
    float mu  = s * (1.0f / DIM);
    float var = ss * (1.0f / DIM) - mu * mu;
    float inv = rsqrtf(var + LN_EPS);
    const float4* wv = (const float4*)w;
    const float4* bv = (const float4*)bias;
    #pragma unroll
    for (int i = 0; i < 6; i++) {
        int idx4 = lane + i * 32;
        float4 ww = wv[idx4], bb = bv[idx4];
        float y0 = (v[i].x - mu) * inv * ww.x + bb.x;
        float y1 = (v[i].y - mu) * inv * ww.y + bb.y;
        float y2 = (v[i].z - mu) * inv * ww.z + bb.z;
        float y3 = (v[i].w - mu) * inv * ww.w + bb.w;
        uint32_t h01, l01, h23, l23;
        pack_split(y0, y1, h01, l01);
        pack_split(y2, y3, h23, l23);
        uint32_t* ph = (uint32_t*)(yh + (size_t)row * DIM) + idx4 * 2;
        uint32_t* pl = (uint32_t*)(yl + (size_t)row * DIM) + idx4 * 2;
        ph[0] = h01; ph[1] = h23;
        pl[0] = l01; pl[1] = l23;
    }
}

// ============================================================================
// Tensor-core GEMM (bf16x3 split, fp32 accum), 3-stage cp.async pipeline,
// 2 CTAs/SM pinned, hoisted addressing, optional split-K via gridDim.z.
// ============================================================================
#define STG_BYTES 32768
#define MMA_SMEM  (3 * STG_BYTES)   // 98304

__global__ __launch_bounds__(256, 2) void mma_gemm_kernel(
    int K, int N,
    const __nv_bfloat16* __restrict__ Ah, const __nv_bfloat16* __restrict__ Al,
    const __nv_bfloat16* __restrict__ Bh, const __nv_bfloat16* __restrict__ Bl,
    const float* __restrict__ bias, const float* __restrict__ resid,
    float* __restrict__ outf,
    __nv_bfloat16* __restrict__ oh, __nv_bfloat16* __restrict__ ol,
    int gelu)
{
    extern __shared__ char smem[];
    uint32_t sbase = smem_u32(smem);
    int tid = threadIdx.x, wid = tid >> 5, lane = tid & 31;
    int n0 = blockIdx.x * 128, m0 = blockIdx.y * 128;

    // split-K range
    int nch_tot = K / 32;
    int per = nch_tot / gridDim.z;
    int ch_begin = blockIdx.z * per;
    int chend = ch_begin + per;

    // hoisted cp.async addressing
    int r_cp = tid >> 2, c_cp = tid & 3;
    uint32_t soff0 = SW128((uint32_t)(r_cp * 64 + c_cp * 16));
    uint32_t soff1 = SW128((uint32_t)((r_cp + 64) * 64 + c_cp * 16));
    size_t goff0 = ((size_t)r_cp * K + c_cp * 8) * 2;
    size_t goff1 = ((size_t)(r_cp + 64) * K + c_cp * 8) * 2;
    const char* pAh = (const char*)(Ah + (size_t)m0 * K);
    const char* pAl = (const char*)(Al + (size_t)m0 * K);
    const char* pBh = (const char*)(Bh + (size_t)n0 * K);
    const char* pBl = (const char*)(Bl + (size_t)n0 * K);

#define ISSUE(CH) do { \
    if ((CH) < chend) { \
        uint32_t sb0 = sbase + (uint32_t)((CH) % 3) * STG_BYTES; \
        size_t kb = (size_t)(CH) * 64; \
        cp16(sb0 +          soff0, pAh + kb + goff0); \
        cp16(sb0 +          soff1, pAh + kb + goff1); \
        cp16(sb0 + 8192  +  soff0, pAl + kb + goff0); \
        cp16(sb0 + 8192  +  soff1, pAl + kb + goff1); \
        cp16(sb0 + 16384 +  soff0, pBh + kb + goff0); \
        cp16(sb0 + 16384 +  soff1, pBh + kb + goff1); \
        cp16(sb0 + 24576 +  soff0, pBl + kb + goff0); \
        cp16(sb0 + 24576 +  soff1, pBl + kb + goff1); \
    } \
    CP_COMMIT(); } while (0)

    int wm = wid >> 2, wn = wid & 3;
    uint32_t lrow = lane & 15, lhalf = lane >> 4;

    // hoisted ldmatrix swizzled offsets (lo tile = hi addr + 8192)
    uint32_t aoff[2][4], boff[2][2];
    #pragma unroll
    for (int ks = 0; ks < 2; ks++) {
        uint32_t koff = (uint32_t)(ks * 2 + lhalf) * 16;
        #pragma unroll
        for (int mf = 0; mf < 4; mf++)
            aoff[ks][mf] = SW128((uint32_t)((wm * 64 + mf * 16 + lrow) * 64) + koff);
        #pragma unroll
        for (int nf2 = 0; nf2 < 2; nf2++)
            boff[ks][nf2] = SW128((uint32_t)((wn * 32 + nf2 * 16 + lrow) * 64) + koff);
    }

    float acc[4][4][4] = {};

    ISSUE(ch_begin);
    ISSUE(ch_begin + 1);

    for (int ch = ch_begin; ch < chend; ch++) {
        CP_WAIT1();
        __syncthreads();
        ISSUE(ch + 2);
        uint32_t st = sbase + (uint32_t)(ch % 3) * STG_BYTES;
        #pragma unroll
        for (int ks = 0; ks < 2; ks++) {
            uint32_t ah[4][4], al[4][4], bh[4][2], bl[4][2];
            #pragma unroll
            for (int mf = 0; mf < 4; mf++) {
                uint32_t a0 = st + aoff[ks][mf];
                LDSM_X4(ah[mf][0], ah[mf][1], ah[mf][2], ah[mf][3], a0);
                LDSM_X4(al[mf][0], al[mf][1], al[mf][2], al[mf][3], a0 + 8192);
            }
            #pragma unroll
            for (int nf2 = 0; nf2 < 2; nf2++) {
                uint32_t b0 = st + 16384 + boff[ks][nf2];
                uint32_t t0, t1, t2, t3;
                LDSM_X4(t0, t1, t2, t3, b0);
                bh[nf2 * 2][0] = t0; bh[nf2 * 2 + 1][0] = t1;
                bh[nf2 * 2][1] = t2; bh[nf2 * 2 + 1][1] = t3;
                LDSM_X4(t0, t1, t2, t3, b0 + 8192);
                bl[nf2 * 2][0] = t0; bl[nf2 * 2 + 1][0] = t1;
                bl[nf2 * 2][1] = t2; bl[nf2 * 2 + 1][1] = t3;
            }
            #pragma unroll
            for (int mf = 0; mf < 4; mf++) {
                #pragma unroll
                for (int nf = 0; nf < 4; nf++) {
                    mma_bf16(acc[mf][nf], ah[mf], bh[nf]);
                    mma_bf16(acc[mf][nf], ah[mf], bl[nf]);
                    mma_bf16(acc[mf][nf], al[mf], bh[nf]);
                }
            }
        }
    }
#undef ISSUE

    // Epilogue
    float* myout = outf ? (outf + (size_t)blockIdx.z * ((size_t)ROWS * N)) : (float*)0;
    int g = lane >> 2, tg = lane & 3;
    #pragma unroll
    for (int mf = 0; mf < 4; mf++) {
        #pragma unroll
        for (int nf = 0; nf < 4; nf++) {
            int col = n0 + wn * 32 + nf * 8 + tg * 2;
            float bv0 = bias ? __ldg(bias + col)     : 0.f;
            float bv1 = bias ? __ldg(bias + col + 1) : 0.f;
            #pragma unroll
            for (int half = 0; half < 2; half++) {
                int row = m0 + wm * 64 + mf * 16 + g + half * 8;
                float v0 = acc[mf][nf][half * 2 + 0] + bv0;
                float v1 = acc[mf][nf][half * 2 + 1] + bv1;
                if (gelu) { v0 = gelu_f(v0); v1 = gelu_f(v1); }
                size_t gb = (size_t)row * N + col;
                if (resid) {
                    float2 rr = *(const float2*)(resid + gb);
                    v0 += rr.x; v1 += rr.y;
                }
                if (myout) {
                    *(float2*)(myout + gb) = make_float2(v0, v1);
                } else {
                    __nv_bfloat16 h0, l0, h1, l1;
                    split2(v0, h0, l0); split2(v1, h1, l1);
                    *(__nv_bfloat162*)(oh + gb) = __nv_bfloat162(h0, h1);
                    *(__nv_bfloat162*)(ol + gb) = __nv_bfloat162(l0, l1);
                }
            }
        }
    }
}

// ============================================================================
// Flash attention via mma.sync (bf16 split Q,K,V,P; fp32 softmax/accum).
// 2 CTAs/SM.  Q parked in dedicated smem; fragments re-loaded per K-tile.
// ============================================================================
#define ATT_SMEM 98304

__device__ __forceinline__ void attn_issue(
    int kt, int tid, uint32_t sb,
    const __nv_bfloat16* qh, const __nv_bfloat16* ql,
    size_t batch_row0, int kcol, int vcol)
{
    if (kt < 16) {
        uint32_t st = sb + (uint32_t)(kt & 1) * 32768;
        size_t rb = batch_row0 + (size_t)kt * 64;
        #pragma unroll
        for (int i = 0; i < 2; i++) {
            int idx = tid + i * 256;
            int r = idx >> 3, c = idx & 7;
            size_t rowoff = (rb + r) * QKV3;
            uint32_t so = SW128((uint32_t)(r * 128 + c * 16));
            cp16(st +         so, (const char*)(qh + rowoff + kcol) + c * 16);
            cp16(st + 8192  + so, (const char*)(ql + rowoff + kcol) + c * 16);
            cp16(st + 16384 + so, (const char*)(qh + rowoff + vcol) + c * 16);
            cp16(st + 24576 + so, (const char*)(ql + rowoff + vcol) + c * 16);
        }
    }
    CP_COMMIT();
}

__global__ __launch_bounds__(256, 2) void flash_mma_kernel(
    const __nv_bfloat16* __restrict__ qh, const __nv_bfloat16* __restrict__ ql,
    __nv_bfloat16* __restrict__ oh, __nv_bfloat16* __restrict__ ol)
{
    extern __shared__ char smem[];
    uint32_t sb = smem_u32(smem);
    int tid = threadIdx.x, wid = tid >> 5, lane = tid & 31;
    int qt = blockIdx.x;
    int b = blockIdx.y / HEADS, h = blockIdx.y % HEADS;
    int g = lane >> 2, tg = lane & 3;
    size_t batch_row0 = (size_t)b * NTOK;
    size_t qrow0 = batch_row0 + (size_t)qt * 128;
    int qcol = h * 64, kcol = DIM + h * 64, vcol = 2 * DIM + h * 64;

    // Stage Q into dedicated region [64KB..96KB): hi at +65536, lo at +81920
    #pragma unroll
    for (int i = 0; i < 4; i++) {
        int idx = tid + i * 256;
        int r = idx >> 3, c = idx & 7;
        size_t rowoff = (qrow0 + r) * QKV3 + qcol;
        uint32_t so = SW128((uint32_t)(r * 128 + c * 16));
        *(uint4*)(smem + 65536 + so) = *((const uint4*)(qh + rowoff) + c);
        *(uint4*)(smem + 81920 + so) = *((const uint4*)(ql + rowoff) + c);
    }

    uint32_t qoff[4];
    {
        uint32_t lrow = lane & 15, lh = lane >> 4;
        #pragma unroll
        for (int kf = 0; kf < 4; kf++)
            qoff[kf] = SW128((uint32_t)((wid * 16 + lrow) * 128) + kf * 32 + lh * 16);
    }
    __syncthreads();

    float m0v = -1e30f, m1v = -1e30f, l0 = 0.f, l1 = 0.f;
    float oacc[8][4] = {};
    const float scale = 0.125f;

    attn_issue(0, tid, sb, qh, ql, batch_row0, kcol, vcol);

    for (int kt = 0; kt < 16; kt++) {
        attn_issue(kt + 1, tid, sb, qh, ql, batch_row0, kcol, vcol);
        CP_WAIT1();
        __syncthreads();
        uint32_t kb = sb + (uint32_t)(kt & 1) * 32768;

        float sc[8][4] = {};
        #pragma unroll
        for (int kf = 0; kf < 4; kf++) {
            uint32_t ah[4], al[4];
            LDSM_X4(ah[0], ah[1], ah[2], ah[3], sb + 65536 + qoff[kf]);
            LDSM_X4(al[0], al[1], al[2], al[3], sb + 81920 + qoff[kf]);
            #pragma unroll
            for (int kg = 0; kg < 4; kg++) {
                uint32_t ro = (uint32_t)((kg * 16 + (lane & 15)) * 128) + kf * 32 + (lane >> 4) * 16;
                uint32_t t0, t1, t2, t3, u0, u1, u2, u3;
                LDSM_X4(t0, t1, t2, t3, kb + SW128(ro));
                LDSM_X4(u0, u1, u2, u3, kb + 8192 + SW128(ro));
                mma4(sc[2 * kg],     ah, t0, t2);
                mma4(sc[2 * kg],     ah, u0, u2);
                mma4(sc[2 * kg],     al, t0, t2);
                mma4(sc[2 * kg + 1], ah, t1, t3);
                mma4(sc[2 * kg + 1], ah, u1, u3);
                mma4(sc[2 * kg + 1], al, t1, t3);
            }
        }

        float mx0 = -1e30f, mx1 = -1e30f;
        #pragma unroll
        for (int nf = 0; nf < 8; nf++) {
            #pragma unroll
            for (int i = 0; i < 4; i++) sc[nf][i] *= scale;
            mx0 = fmaxf(mx0, fmaxf(sc[nf][0], sc[nf][1]));
            mx1 = fmaxf(mx1, fmaxf(sc[nf][2], sc[nf][3]));
        }
        mx0 = fmaxf(mx0, __shfl_xor_sync(0xffffffffu, mx0, 1));
        mx0 = fmaxf(mx0, __shfl_xor_sync(0xffffffffu, mx0, 2));
        mx1 = fmaxf(mx1, __shfl_xor_sync(0xffffffffu, mx1, 1));
        mx1 = fmaxf(mx1, __shfl_xor_sync(0xffffffffu, mx1, 2));
        float nm0 = fmaxf(m0v, mx0), nm1 = fmaxf(m1v, mx1);
        float c0 = __expf(m0v - nm0), c1 = __expf(m1v - nm1);
        l0 *= c0; l1 *= c1;
        #pragma unroll
        for (int nf = 0; nf < 8; nf++) {
            oacc[nf][0] *= c0; oacc[nf][1] *= c0;
            oacc[nf][2] *= c1; oacc[nf][3] *= c1;
        }
        m0v = nm0; m1v = nm1;
        float ps0 = 0.f, ps1 = 0.f;
        #pragma unroll
        for (int nf = 0; nf < 8; nf++) {
            sc[nf][0] = __expf(sc[nf][0] - nm0);
            sc[nf][1] = __expf(sc[nf][1] - nm0);
            sc[nf][2] = __expf(sc[nf][2] - nm1);
            sc[nf][3] = __expf(sc[nf][3] - nm1);
            ps0 += sc[nf][0] + sc[nf][1];
            ps1 += sc[nf][2] + sc[nf][3];
        }
        ps0 += __shfl_xor_sync(0xffffffffu, ps0, 1);
        ps0 += __shfl_xor_sync(0xffffffffu, ps0, 2);
        ps1 += __shfl_xor_sync(0xffffffffu, ps1, 1);
        ps1 += __shfl_xor_sync(0xffffffffu, ps1, 2);
        l0 += ps0; l1 += ps1;

        #pragma unroll
        for (int c = 0; c < 4; c++) {
            uint32_t pah[4], pal[4];
            pack_split(sc[2 * c][0],     sc[2 * c][1],     pah[0], pal[0]);
            pack_split(sc[2 * c][2],     sc[2 * c][3],     pah[1], pal[1]);
            pack_split(sc[2 * c + 1][0], sc[2 * c + 1][1], pah[2], pal[2]);
            pack_split(sc[2 * c + 1][2], sc[2 * c + 1][3], pah[3], pal[3]);
            #pragma unroll
            for (int dg = 0; dg < 4; dg++) {
                uint32_t ro = (uint32_t)((c * 16 + (lane & 15)) * 128) + dg * 32 + (lane >> 4) * 16;
                uint32_t t0, t1, t2, t3, u0, u1, u2, u3;
                LDSM_X4_T(t0, t1, t2, t3, kb + 16384 + SW128(ro));
                LDSM_X4_T(u0, u1, u2, u3, kb + 24576 + SW128(ro));
                mma4(oacc[2 * dg],     pah, t0, t1);
                mma4(oacc[2 * dg],     pah, u0, u1);
                mma4(oacc[2 * dg],     pal, t0, t1);
                mma4(oacc[2 * dg + 1], pah, t2, t3);
                mma4(oacc[2 * dg + 1], pah, u2, u3);
                mma4(oacc[2 * dg + 1], pal, t2, t3);
            }
        }
        __syncthreads();
    }

    float inv0 = 1.f / l0, inv1 = 1.f / l1;
    size_t r0 = qrow0 + wid * 16 + g;
    #pragma unroll
    for (int nf = 0; nf < 8; nf++) {
        int col = h * 64 + nf * 8 + tg * 2;
        float v0 = oacc[nf][0] * inv0, v1 = oacc[nf][1] * inv0;
        float v2 = oacc[nf][2] * inv1, v3 = oacc[nf][3] * inv1;
        __nv_bfloat16 h0, lo0, h1, lo1;
        split2(v0, h0, lo0); split2(v1, h1, lo1);
        *(__nv_bfloat162*)(oh + r0 * DIM + col) = __nv_bfloat162(h0, h1);
        *(__nv_bfloat162*)(ol + r0 * DIM + col) = __nv_bfloat162(lo0, lo1);
        split2(v2, h0, lo0); split2(v3, h1, lo1);
        *(__nv_bfloat162*)(oh + (r0 + 8) * DIM + col) = __nv_bfloat162(h0, h1);
        *(__nv_bfloat162*)(ol + (r0 + 8) * DIM + col) = __nv_bfloat162(lo0, lo1);
    }
}

// ============================================================================
// Final transpose with fused split-K=3 reduce:
// out[b,d,n] = x[b,n,d] + part0 + part1 + part2 + bias[d]
// ============================================================================
__global__ void transpose_out_kernel(const float* __restrict__ x,
                                     const float* __restrict__ part,
                                     const float* __restrict__ bias,
                                     float* __restrict__ out)
{
    __shared__ float t[32][33];
    int b = blockIdx.z;
    int n0 = blockIdx.x * 32, d0 = blockIdx.y * 32;
    int tx = threadIdx.x, ty = threadIdx.y;
    float bv = bias[d0 + tx];
    for (int i = ty; i < 32; i += 8) {
        size_t idx = ((size_t)b * NTOK + n0 + i) * DIM + d0 + tx;
        t[i][tx] = x[idx] + part[idx] + part[(size_t)ROWS * DIM + idx]
                 + part[(size_t)2 * ROWS * DIM + idx] + bv;
    }
    __syncthreads();
    for (int i = ty; i < 32; i += 8)
        out[((size_t)b * DIM + d0 + i) * NTOK + n0 + tx] = t[tx][i];
}

// ============================================================================
// Host orchestration
// ============================================================================
extern "C" void kernel_launch(void* const* d_in, const int* in_sizes, int n_in,
                              void* d_out, int out_size)
{
    const float* c_f    = (const float*)d_in[0];
    const float* conv_w = (const float*)d_in[1];
    const float* conv_b = (const float*)d_in[2];
    const float* ln1_w  = (const float*)d_in[3];
    const float* ln1_b  = (const float*)d_in[4];
    const float* qkv_w  = (const float*)d_in[5];
    const float* out_w  = (const float*)d_in[6];
    const float* out_b  = (const float*)d_in[7];
    const float* ln2_w  = (const float*)d_in[8];
    const float* ln2_b  = (const float*)d_in[9];
    const float* mlp_w1 = (const float*)d_in[10];
    const float* mlp_b1 = (const float*)d_in[11];
    const float* mlp_w2 = (const float*)d_in[12];
    const float* mlp_b2 = (const float*)d_in[13];
    float* out = (float*)d_out;

    cudaFuncSetAttribute(mma_gemm_kernel,
                         cudaFuncAttributeMaxDynamicSharedMemorySize, MMA_SMEM);
    cudaFuncSetAttribute(flash_mma_kernel,
                         cudaFuncAttributeMaxDynamicSharedMemorySize, ATT_SMEM);

    float *p_x, *p_part;
    __nv_bfloat16 *p_yh, *p_yl, *p_oh, *p_ol, *p_hh, *p_hl, *p_qh, *p_ql;
    __nv_bfloat16 *p_qwh, *p_qwl, *p_owh, *p_owl, *p_m1h, *p_m1l, *p_m2h, *p_m2l;
    cudaGetSymbolAddress((void**)&p_x,    g_x);
    cudaGetSymbolAddress((void**)&p_part, g_part);
    cudaGetSymbolAddress((void**)&p_yh,  g_yh);
    cudaGetSymbolAddress((void**)&p_yl,  g_yl);
    cudaGetSymbolAddress((void**)&p_oh,  g_oh);
    cudaGetSymbolAddress((void**)&p_ol,  g_ol);
    cudaGetSymbolAddress((void**)&p_hh,  g_hh);
    cudaGetSymbolAddress((void**)&p_hl,  g_hl);
    cudaGetSymbolAddress((void**)&p_qh,  g_qh);
    cudaGetSymbolAddress((void**)&p_ql,  g_ql);
    cudaGetSymbolAddress((void**)&p_qwh, g_qkvw_h);
    cudaGetSymbolAddress((void**)&p_qwl, g_qkvw_l);
    cudaGetSymbolAddress((void**)&p_owh, g_outw_h);
    cudaGetSymbolAddress((void**)&p_owl, g_outw_l);
    cudaGetSymbolAddress((void**)&p_m1h, g_m1w_h);
    cudaGetSymbolAddress((void**)&p_m1l, g_m1w_l);
    cudaGetSymbolAddress((void**)&p_m2h, g_m2w_h);
    cudaGetSymbolAddress((void**)&p_m2l, g_m2w_l);

    wsplit_all_kernel<<<DEPTH * WL_BLOCKS, dim3(32, 8)>>>(
        qkv_w, out_w, mlp_w1, mlp_w2,
        p_qwh, p_qwl, p_owh, p_owl, p_m1h, p_m1l, p_m2h, p_m2l);

    embed_kernel<<<dim3(NTOK / 64, DIM / 64, BATCH), 256>>>(c_f, conv_w, conv_b, p_x);

    // layer 0 LN1 (no pending split-K reduce)
    ln_split_kernel<<<ROWS / 8, 256>>>(nullptr, nullptr, p_x,
                                       ln1_w, ln1_b, p_yh, p_yl);

    for (int l = 0; l < DEPTH; l++) {
        mma_gemm_kernel<<<dim3(QKV3 / 128, ROWS / 128, 1), 256, MMA_SMEM>>>(
            DIM, QKV3, p_yh, p_yl,
            p_qwh + (size_t)l * QKV3 * DIM, p_qwl + (size_t)l * QKV3 * DIM,
            nullptr, nullptr, nullptr, p_qh, p_ql, 0);
        flash_mma_kernel<<<dim3(NTOK / 128, BATCH * HEADS), 256, ATT_SMEM>>>(
            p_qh, p_ql, p_oh, p_ol);
        // attn out-proj: split-K=3 -> partials; reduce fused into LN2
        mma_gemm_kernel<<<dim3(DIM / 128, ROWS / 128, 3), 256, MMA_SMEM>>>(
            DIM, DIM, p_oh, p_ol,
            p_owh + (size_t)l * DIM * DIM, p_owl + (size_t)l * DIM * DIM,
            nullptr, nullptr, p_part, nullptr, nullptr, 0);
        ln_split_kernel<<<ROWS / 8, 256>>>(p_part, out_b + l * DIM, p_x,
                                           ln2_w + l * DIM, ln2_b + l * DIM,
                                           p_yh, p_yl);
        mma_gemm_kernel<<<dim3(MLPD / 128, ROWS / 128, 1), 256, MMA_SMEM>>>(
            DIM, MLPD, p_yh, p_yl,
            p_m1h + (size_t)l * MLPD * DIM, p_m1l + (size_t)l * MLPD * DIM,
            mlp_b1 + l * MLPD, nullptr, nullptr, p_hh, p_hl, 1);
        // mlp2: split-K=3 -> partials; reduce fused into next layer's LN1
        // (last layer: reduce fused into the final transpose)
        mma_gemm_kernel<<<dim3(DIM / 128, ROWS / 128, 3), 256, MMA_SMEM>>>(
            MLPD, DIM, p_hh, p_hl,
            p_m2h + (size_t)l * DIM * MLPD, p_m2l + (size_t)l * DIM * MLPD,
            nullptr, nullptr, p_part, nullptr, nullptr, 0);
        if (l < DEPTH - 1) {
            ln_split_kernel<<<ROWS / 8, 256>>>(p_part, mlp_b2 + l * DIM, p_x,
                                               ln1_w + (l + 1) * DIM,
                                               ln1_b + (l + 1) * DIM,
                                               p_yh, p_yl);
        }
    }

    transpose_out_kernel<<<dim3(NTOK / 32, DIM / 32, BATCH), dim3(32, 8)>>>(
        p_x, p_part, mlp_b2 + (DEPTH - 1) * DIM, out);
}